// round 1
// baseline (speedup 1.0000x reference)
#include <cuda_runtime.h>
#include <math.h>

#define NB 16
#define CI 512
#define CO 512
#define RES 64
#define YS 66      // conv output spatial (64 + 2*2 - 3 + 1)
#define US 138     // upsampled spatial
#define OS 64      // final output spatial

// ---------------- scratch (device globals: allocation-free) ----------------
__device__ float g_styles[NB * CI];
__device__ float g_s[NB * CI];
__device__ float g_ssum[1];
__device__ float g_wt[CI * CO * 9];   // layout [i][o][k]  (k = ky*3+kx)
__device__ float g_q[CO * CI];        // [o][i] = sum_k wt^2
__device__ float g_d[NB * CO];
__device__ float g_y[NB * CO * YS * YS];            // 142 MB
__device__ float g_uv[NB * CO * US * YS];           // 298 MB
__device__ float g_u [156008448];                   // NB*CO*US*US, 624 MB
__device__ float g_dv[NB * CO * OS * US];           // 289 MB

// ---------------- setup kernels ----------------
__global__ void k_init() { g_ssum[0] = 0.f; }

// styles[n,c] = (w[n,:] . aw[c,:]) / sqrt(512) + ab[c]; accumulate sum(styles^2)
__global__ void k_styles(const float* __restrict__ w,
                         const float* __restrict__ aw,
                         const float* __restrict__ ab) {
    int n = blockIdx.x, c = threadIdx.x;
    const float* wr = w + n * 512;
    const float* ar = aw + c * 512;
    float acc = 0.f;
    #pragma unroll 8
    for (int k = 0; k < 512; k++) acc += wr[k] * ar[k];
    float st = acc * 0.044194173824159216f + ab[c];   // 1/sqrt(512)
    g_styles[n * CI + c] = st;
    float v = st * st;
    #pragma unroll
    for (int off = 16; off; off >>= 1) v += __shfl_down_sync(0xffffffffu, v, off);
    if ((threadIdx.x & 31) == 0) atomicAdd(g_ssum, v);
}

// s = styles * rsqrt(mean(styles^2))
__global__ void k_norm_s() {
    int i = blockIdx.x * 512 + threadIdx.x;
    float msr = rsqrtf(g_ssum[0] * (1.0f / (NB * CI)));
    g_s[i] = g_styles[i] * msr;
}

// wt[o,i,k] = cw * rsqrt(mean_{i,k} cw^2);  q[o,i] = sum_k wt^2
__global__ void k_wt(const float* __restrict__ cw) {
    int o = blockIdx.x, i = threadIdx.x;
    float wl[9]; float ss = 0.f;
    const float* p = cw + (o * CI + i) * 9;
    #pragma unroll
    for (int k = 0; k < 9; k++) { wl[k] = p[k]; ss += wl[k] * wl[k]; }
    __shared__ float red[512];
    red[i] = ss;
    __syncthreads();
    for (int s = 256; s; s >>= 1) { if (i < s) red[i] += red[i + s]; __syncthreads(); }
    float inv = rsqrtf(red[0] * (1.0f / 4608.0f));
    #pragma unroll
    for (int k = 0; k < 9; k++) g_wt[(i * CO + o) * 9 + k] = wl[k] * inv;
    g_q[o * CI + i] = ss * inv * inv;
}

// d[n,o] = rsqrt( sum_i s[n,i]^2 * q[o,i] + 1e-8 )
__global__ void k_d() {
    int idx = blockIdx.x * 256 + threadIdx.x;   // 8192
    int n = idx & 15, o = idx >> 4;
    const float* sp = g_s + n * CI;
    const float* qp = g_q + o * CI;
    float acc = 0.f;
    #pragma unroll 4
    for (int i = 0; i < CI; i++) { float sv = sp[i]; acc += sv * sv * qp[i]; }
    g_d[n * CO + o] = rsqrtf(acc + 1e-8f);
}

// ---------------- conv: y[n,o,py,px] = d[n,o]*sum_{i,k} wt[i,o,k]*s[n,i]*x[...] + cb[o]
#define TOC 32    // out-channel tile
#define TP  16    // pixel tile (16x16)
#define ICC 8     // input channels per smem stage
__global__ void __launch_bounds__(256, 2)
k_conv(const float* __restrict__ x, const float* __restrict__ cb) {
    __shared__ float sX[ICC][18 * 21];   // 18 rows, stride 21
    __shared__ float sW[ICC][TOC * 9];

    int n   = blockIdx.z;
    int oc0 = blockIdx.y * TOC;
    int ty  = blockIdx.x / 5, tx = blockIdx.x % 5;
    int py0 = ty * TP, px0 = tx * TP;

    int tid  = threadIdx.x;
    int t_px = tid & 15, t_oc = tid >> 4;
    int pyt  = t_px >> 2, pxt = t_px & 3;   // thread covers 4x4 px, 2 oc

    float acc[2][4][4];
    #pragma unroll
    for (int a = 0; a < 2; a++)
        #pragma unroll
        for (int b = 0; b < 4; b++)
            #pragma unroll
            for (int c = 0; c < 4; c++) acc[a][b][c] = 0.f;

    const float* sPtr = g_s + n * CI;

    for (int ic0 = 0; ic0 < CI; ic0 += ICC) {
        __syncthreads();
        // stage X tile (with modulation s folded in) : ICC x 18 x 18
        for (int e = tid; e < ICC * 18 * 18; e += 256) {
            int ic = e / 324; int r = e - ic * 324;
            int rr = r / 18;  int cc = r - rr * 18;
            int gy = py0 - 2 + rr, gx = px0 - 2 + cc;
            float v = 0.f;
            if (gy >= 0 && gy < RES && gx >= 0 && gx < RES)
                v = x[((n * CI + ic0 + ic) * RES + gy) * RES + gx] * sPtr[ic0 + ic];
            sX[ic][rr * 21 + cc] = v;
        }
        // stage W tile: ICC x 32 x 9, contiguous per ic
        for (int e = tid; e < ICC * TOC * 9; e += 256) {
            int ic = e / (TOC * 9); int r = e - ic * TOC * 9;
            sW[ic][r] = g_wt[((ic0 + ic) * CO + oc0) * 9 + r];
        }
        __syncthreads();

        #pragma unroll
        for (int ic = 0; ic < ICC; ic++) {
            float xv[6][6];
            #pragma unroll
            for (int yy = 0; yy < 6; yy++)
                #pragma unroll
                for (int xx = 0; xx < 6; xx++)
                    xv[yy][xx] = sX[ic][(pyt * 4 + yy) * 21 + pxt * 4 + xx];
            float wv[2][9];
            #pragma unroll
            for (int o2 = 0; o2 < 2; o2++)
                #pragma unroll
                for (int k = 0; k < 9; k++)
                    wv[o2][k] = sW[ic][(t_oc * 2 + o2) * 9 + k];
            #pragma unroll
            for (int o2 = 0; o2 < 2; o2++)
                #pragma unroll
                for (int ky = 0; ky < 3; ky++)
                    #pragma unroll
                    for (int kx = 0; kx < 3; kx++)
                        #pragma unroll
                        for (int yy = 0; yy < 4; yy++)
                            #pragma unroll
                            for (int xx = 0; xx < 4; xx++)
                                acc[o2][yy][xx] += wv[o2][ky * 3 + kx] * xv[yy + ky][xx + kx];
        }
    }

    #pragma unroll
    for (int o2 = 0; o2 < 2; o2++) {
        int oc = oc0 + t_oc * 2 + o2;
        float dd = g_d[n * CO + oc];
        float bb = cb[oc];
        #pragma unroll
        for (int yy = 0; yy < 4; yy++) {
            int py = py0 + pyt * 4 + yy;
            if (py >= YS) continue;
            #pragma unroll
            for (int xx = 0; xx < 4; xx++) {
                int px = px0 + pxt * 4 + xx;
                if (px >= YS) continue;
                g_y[((n * CO + oc) * YS + py) * YS + px] = acc[o2][yy][xx] * dd + bb;
            }
        }
    }
}

// ---------------- filtered_lrelu (separable, 4 passes) ----------------
// up vertical: uv[r,x] = sum_t f[t]*y[(r+t-9)/2, x]  for even (r+t-9) in [0,130]
__global__ void k_upv(const float* __restrict__ f) {
    int ip = blockIdx.x * 256 + threadIdx.x;
    if (ip >= US * YS) return;
    int nc = blockIdx.y;
    int r = ip / YS, xcol = ip - r * YS;
    const float* yb = g_y + nc * (YS * YS) + xcol;
    float acc = 0.f;
    #pragma unroll
    for (int t = 0; t < 12; t++) {
        int m = r + t - 9;
        if (m >= 0 && m <= 130 && !(m & 1)) acc += f[t] * yb[(m >> 1) * YS];
    }
    g_uv[nc * (US * YS) + ip] = acc;
}

// up horizontal + gain(4) + lrelu*sqrt(2) + clamp
__global__ void k_uph(const float* __restrict__ f) {
    int ip = blockIdx.x * 256 + threadIdx.x;
    if (ip >= US * US) return;
    int nc = blockIdx.y;
    int r = ip / US, c = ip - r * US;
    const float* ub = g_uv + (nc * US + r) * YS;
    float acc = 0.f;
    #pragma unroll
    for (int t = 0; t < 12; t++) {
        int m = c + t - 9;
        if (m >= 0 && m <= 130 && !(m & 1)) acc += f[t] * ub[m >> 1];
    }
    float v = acc * 4.0f;
    v = (v >= 0.f ? v : 0.2f * v) * 1.4142135623730951f;
    v = fminf(fmaxf(v, -256.f), 256.f);
    g_u[(nc * US + r) * US + c] = v;
}

// down vertical: dv[oy,c] = sum_t f[t]*u[2oy+t, c]
__global__ void k_downv(const float* __restrict__ f) {
    int ip = blockIdx.x * 256 + threadIdx.x;
    if (ip >= OS * US) return;
    int nc = blockIdx.y;
    int oy = ip / US, c = ip - oy * US;
    const float* ub = g_u + (nc * US + 2 * oy) * US + c;
    float acc = 0.f;
    #pragma unroll
    for (int t = 0; t < 12; t++) acc += f[t] * ub[t * US];
    g_dv[(nc * OS + oy) * US + c] = acc;
}

// down horizontal: out[oy,ox] = sum_t f[t]*dv[oy, 2ox+t]
__global__ void k_downh(const float* __restrict__ f, float* __restrict__ out) {
    int ip = blockIdx.x * 256 + threadIdx.x;
    if (ip >= OS * OS) return;
    int nc = blockIdx.y;
    int oy = ip >> 6, ox = ip & 63;
    const float* db = g_dv + (nc * OS + oy) * US + 2 * ox;
    float acc = 0.f;
    #pragma unroll
    for (int t = 0; t < 12; t++) acc += f[t] * db[t];
    out[nc * (OS * OS) + ip] = acc;
}

// ---------------- launch ----------------
extern "C" void kernel_launch(void* const* d_in, const int* in_sizes, int n_in,
                              void* d_out, int out_size) {
    const float* x  = (const float*)d_in[0];
    const float* w  = (const float*)d_in[1];
    const float* aw = (const float*)d_in[2];
    const float* ab = (const float*)d_in[3];
    const float* cw = (const float*)d_in[4];
    const float* cb = (const float*)d_in[5];
    const float* fu = (const float*)d_in[6];
    const float* fd = (const float*)d_in[7];
    float* out = (float*)d_out;

    k_init<<<1, 1>>>();
    k_styles<<<NB, 512>>>(w, aw, ab);
    k_norm_s<<<NB, 512>>>();
    k_wt<<<CO, 512>>>(cw);
    k_d<<<(NB * CO) / 256, 256>>>();

    dim3 gc(25, CO / TOC, NB);
    k_conv<<<gc, 256>>>(x, cb);

    k_upv  <<<dim3((US * YS + 255) / 256, NB * CO), 256>>>(fu);
    k_uph  <<<dim3((US * US + 255) / 256, NB * CO), 256>>>(fu);
    k_downv<<<dim3((OS * US + 255) / 256, NB * CO), 256>>>(fd);
    k_downh<<<dim3((OS * OS + 255) / 256, NB * CO), 256>>>(fd, out);
}

// round 5
// speedup vs baseline: 3.1926x; 3.1926x over previous
#include <cuda_runtime.h>
#include <cuda_bf16.h>
#include <cstdint>
#include <math.h>

#define NB 16
#define CI 512
#define CO 512
#define RES 64
#define YS 66
#define PSTR 4768
#define YPAD 4608
#define OS 64

// ---------------- scratch (device globals) ----------------
__device__ float g_styles[NB * CI];
__device__ float g_s[NB * CI];
__device__ float g_ssum[1];
__device__ float g_q[CO * CI];
__device__ float g_d[NB * CO];
__device__ __nv_bfloat16 g_wh[9 * CO * CI];            // [k9][o][i]
__device__ __nv_bfloat16 g_wl[9 * CO * CI];
__device__ __nv_bfloat16 g_xh[(size_t)NB * PSTR * CI]; // [n][p][i]
__device__ __nv_bfloat16 g_xl[(size_t)NB * PSTR * CI];
__device__ float g_y[(size_t)NB * CO * YPAD];

// ---------------- helpers ----------------
__device__ __forceinline__ uint32_t smem_u32(const void* p) {
    uint32_t a;
    asm("{ .reg .u64 t; cvta.to.shared.u64 t, %1; cvt.u32.u64 %0, t; }" : "=r"(a) : "l"(p));
    return a;
}
__device__ __forceinline__ void cp16(uint32_t dst, const void* src) {
    asm volatile("cp.async.cg.shared.global [%0], [%1], 16;" :: "r"(dst), "l"(src));
}
__device__ __forceinline__ void ldsm4(uint32_t* r, uint32_t addr) {
    asm volatile("ldmatrix.sync.aligned.m8n8.x4.shared.b16 {%0,%1,%2,%3}, [%4];"
                 : "=r"(r[0]), "=r"(r[1]), "=r"(r[2]), "=r"(r[3]) : "r"(addr));
}
__device__ __forceinline__ void mma16816(float* c, const uint32_t* a, uint32_t b0, uint32_t b1) {
    asm volatile(
        "mma.sync.aligned.m16n8k16.row.col.f32.bf16.bf16.f32 "
        "{%0,%1,%2,%3}, {%4,%5,%6,%7}, {%8,%9}, {%0,%1,%2,%3};"
        : "+f"(c[0]), "+f"(c[1]), "+f"(c[2]), "+f"(c[3])
        : "r"(a[0]), "r"(a[1]), "r"(a[2]), "r"(a[3]), "r"(b0), "r"(b1));
}

// ---------------- setup kernels ----------------
__global__ void k_init() { g_ssum[0] = 0.f; }

__global__ void k_styles(const float* __restrict__ w,
                         const float* __restrict__ aw,
                         const float* __restrict__ ab) {
    int n = blockIdx.x, c = threadIdx.x;
    const float* wr = w + n * 512;
    const float* ar = aw + c * 512;
    float acc = 0.f;
    #pragma unroll 8
    for (int k = 0; k < 512; k++) acc += wr[k] * ar[k];
    float st = acc * 0.044194173824159216f + ab[c];
    g_styles[n * CI + c] = st;
    float v = st * st;
    #pragma unroll
    for (int off = 16; off; off >>= 1) v += __shfl_down_sync(0xffffffffu, v, off);
    if ((threadIdx.x & 31) == 0) atomicAdd(g_ssum, v);
}

__global__ void k_norm_s() {
    int i = blockIdx.x * 512 + threadIdx.x;
    float msr = rsqrtf(g_ssum[0] * (1.0f / (NB * CI)));
    g_s[i] = g_styles[i] * msr;
}

__global__ void k_wt(const float* __restrict__ cw) {
    int o = blockIdx.x, i = threadIdx.x;
    float wl9[9]; float ss = 0.f;
    const float* p = cw + (o * CI + i) * 9;
    #pragma unroll
    for (int k = 0; k < 9; k++) { wl9[k] = p[k]; ss += wl9[k] * wl9[k]; }
    __shared__ float red[512];
    red[i] = ss;
    __syncthreads();
    for (int s = 256; s; s >>= 1) { if (i < s) red[i] += red[i + s]; __syncthreads(); }
    float inv = rsqrtf(red[0] * (1.0f / 4608.0f));
    #pragma unroll
    for (int k = 0; k < 9; k++) {
        float v = wl9[k] * inv;
        __nv_bfloat16 h = __float2bfloat16(v);
        __nv_bfloat16 l = __float2bfloat16(v - __bfloat162float(h));
        g_wh[(k * 512 + o) * 512 + i] = h;
        g_wl[(k * 512 + o) * 512 + i] = l;
    }
    g_q[o * CI + i] = ss * inv * inv;
}

__global__ void k_d() {
    int idx = blockIdx.x * 256 + threadIdx.x;
    int n = idx & 15, o = idx >> 4;
    const float* sp = g_s + n * CI;
    const float* qp = g_q + o * CI;
    float acc = 0.f;
    #pragma unroll 4
    for (int i = 0; i < CI; i++) { float sv = sp[i]; acc += sv * sv * qp[i]; }
    g_d[n * CO + o] = rsqrtf(acc + 1e-8f);
}

// ---------------- x prep: modulate, pad to 68x68, channels-last, split bf16
__global__ void __launch_bounds__(256) k_xsplit(const float* __restrict__ x) {
    int py = blockIdx.x, n = blockIdx.y, t = threadIdx.x;
    size_t obase = ((size_t)n * PSTR + (size_t)py * 68) * 512;
    int ys = py - 2;
    __nv_bfloat16 z = __float2bfloat16(0.f);
    if (ys < 0 || ys >= 64) {
        for (int e = t; e < 68 * 512; e += 256) { g_xh[obase + e] = z; g_xl[obase + e] = z; }
        return;
    }
    for (int e = t; e < 4 * 512; e += 256) {
        int col = e >> 9, i = e & 511;
        int px = (col < 2) ? col : (64 + col);
        g_xh[obase + (size_t)px * 512 + i] = z;
        g_xl[obase + (size_t)px * 512 + i] = z;
    }
    __shared__ float sh[64][65], sl[64][65];
    const float* sp = g_s + n * 512;
    for (int i0 = 0; i0 < 512; i0 += 64) {
        __syncthreads();
        for (int e = t; e < 64 * 64; e += 256) {
            int ii = e >> 6, px = e & 63;
            float v = x[(((size_t)n * 512 + i0 + ii) * 64 + ys) * 64 + px] * sp[i0 + ii];
            float hv = __bfloat162float(__float2bfloat16(v));
            sh[ii][px] = hv;
            sl[ii][px] = v - hv;
        }
        __syncthreads();
        for (int e = t; e < 64 * 64; e += 256) {
            int px = e >> 6, ii = e & 63;
            size_t oi = obase + (size_t)(px + 2) * 512 + i0 + ii;
            g_xh[oi] = __float2bfloat16(sh[ii][px]);
            g_xl[oi] = __float2bfloat16(sl[ii][px]);
        }
    }
}

// ---------------- conv via mma.sync bf16 GEMM ----------------
// CTA: 128 oc x 128 px. Iter = (tap, ic-chunk-32): stage {Ah,Al,Bh,Bl}, 3 mma passes.
#define ROWB 80
#define TILEB 10240
#define STAGEB 40960
#define CONV_SMEM (2 * STAGEB)

__global__ void __launch_bounds__(256) k_conv(const float* __restrict__ cb) {
    extern __shared__ char smem[];
    uint32_t sb = smem_u32(smem);
    int t = threadIdx.x, wid = t >> 5, lane = t & 31;
    int wm = wid & 1, wn = wid >> 1;
    int oc0 = blockIdx.x * 128;
    int p0  = blockIdx.y * 128;
    int n   = blockIdx.z;

    float acc[4][4][4];
    #pragma unroll
    for (int mi = 0; mi < 4; mi++)
        #pragma unroll
        for (int ni = 0; ni < 4; ni++)
            #pragma unroll
            for (int q = 0; q < 4; q++) acc[mi][ni][q] = 0.f;

    auto stage_issue = [&](int it, int buf) {
        int tap = it >> 4, icc = it & 15;
        int ic0 = icc << 5;
        int ky = tap / 3, kx = tap - ky * 3;
        const __nv_bfloat16* ah = g_wh + ((size_t)(tap * 512 + oc0)) * 512 + ic0;
        const __nv_bfloat16* al = g_wl + ((size_t)(tap * 512 + oc0)) * 512 + ic0;
        size_t boff = ((size_t)n * PSTR + p0 + ky * 68 + kx) * 512 + ic0;
        const __nv_bfloat16* bh = g_xh + boff;
        const __nv_bfloat16* bl = g_xl + boff;
        uint32_t sbase = sb + buf * STAGEB;
        #pragma unroll
        for (int j = 0; j < 8; j++) {
            int id = j * 256 + t;
            int tile = id >> 9, e = id & 511;
            int row = e >> 2, c16 = e & 3;
            const __nv_bfloat16* src =
                (tile == 0) ? ah : (tile == 1) ? al : (tile == 2) ? bh : bl;
            cp16(sbase + tile * TILEB + row * ROWB + c16 * 16,
                 src + (size_t)row * 512 + c16 * 8);
        }
        asm volatile("cp.async.commit_group;" ::: "memory");
    };

    stage_issue(0, 0);

    int rl = lane & 15, chh = lane >> 4;
    for (int it = 0; it < 144; it++) {
        int buf = it & 1;
        if (it + 1 < 144) {
            stage_issue(it + 1, buf ^ 1);
            asm volatile("cp.async.wait_group 1;" ::: "memory");
        } else {
            asm volatile("cp.async.wait_group 0;" ::: "memory");
        }
        __syncthreads();

        uint32_t sbase = sb + buf * STAGEB;
        #pragma unroll
        for (int pass = 0; pass < 3; pass++) {
            uint32_t At = sbase + ((pass == 1) ? TILEB : 0);
            uint32_t Bt = sbase + ((pass == 2) ? 3 * TILEB : 2 * TILEB);
            #pragma unroll
            for (int kk = 0; kk < 2; kk++) {
                uint32_t a[4][4], b[2][4];
                #pragma unroll
                for (int mi = 0; mi < 4; mi++)
                    ldsm4(a[mi], At + (wm * 64 + mi * 16 + rl) * ROWB + (kk * 2 + chh) * 16);
                #pragma unroll
                for (int nj = 0; nj < 2; nj++)
                    ldsm4(b[nj], Bt + (wn * 32 + nj * 16 + rl) * ROWB + (kk * 2 + chh) * 16);
                #pragma unroll
                for (int mi = 0; mi < 4; mi++)
                    #pragma unroll
                    for (int ni = 0; ni < 4; ni++) {
                        int nj = ni >> 1, sub = ni & 1;
                        mma16816(acc[mi][ni], a[mi], b[nj][sub], b[nj][sub + 2]);
                    }
            }
        }
        __syncthreads();
    }

    // ---- epilogue: demod + bias, write g_y ----
    int g4 = lane >> 2, t4 = lane & 3;
    #pragma unroll
    for (int mi = 0; mi < 4; mi++) {
        int oc_a = oc0 + wm * 64 + mi * 16 + g4;
        int oc_b = oc_a + 8;
        float da = g_d[n * CO + oc_a], ba = cb[oc_a];
        float db = g_d[n * CO + oc_b], bb = cb[oc_b];
        float* ya = g_y + ((size_t)(n * CO + oc_a)) * YPAD + p0;
        float* yb = g_y + ((size_t)(n * CO + oc_b)) * YPAD + p0;
        #pragma unroll
        for (int ni = 0; ni < 4; ni++) {
            int px = wn * 32 + ni * 8 + t4 * 2;
            float2 va, vb;
            va.x = acc[mi][ni][0] * da + ba;
            va.y = acc[mi][ni][1] * da + ba;
            vb.x = acc[mi][ni][2] * db + bb;
            vb.y = acc[mi][ni][3] * db + bb;
            *(float2*)(ya + px) = va;
            *(float2*)(yb + px) = vb;
        }
    }
}

// ---------------- fused filtered_lrelu: one CTA per (n,c) image ----------------
#define F_SY 0
#define F_SUV 4488
#define F_SU (4488 + 9384)
#define F_SDV (13872 + 5977)
#define F_SF (19849 + 2224)
#define FIR_SMEM ((22073 + 24) * 4)

__global__ void __launch_bounds__(256, 2) k_fir(const float* __restrict__ fu,
                                                const float* __restrict__ fd,
                                                float* __restrict__ out) {
    extern __shared__ float sm[];
    float* sY  = sm + F_SY;
    float* sUV = sm + F_SUV;
    float* sU  = sm + F_SU;
    float* sDV = sm + F_SDV;
    float* sF  = sm + F_SF;
    int t = threadIdx.x;
    int nc = blockIdx.x;

    if (t < 12) sF[t] = fu[t];
    else if (t < 24) sF[t] = fd[t - 12];
    const float4* gy = (const float4*)(g_y + (size_t)nc * YPAD);
    float4* sY4 = (float4*)sY;
    for (int e = t; e < 1122; e += 256) sY4[e] = gy[e];
    __syncthreads();

    for (int e = t; e < 138 * 66; e += 256) {
        int r = e / 66, xx = e - r * 66;
        int tp0 = (r + 1) & 1;
        float acc = 0.f;
        #pragma unroll
        for (int j = 0; j < 6; j++) {
            int tp = tp0 + 2 * j;
            int m = r + tp - 9;
            if (m >= 0 && m <= 130) acc += sF[tp] * sY[(m >> 1) * 68 + xx];
        }
        sUV[r * 68 + xx] = acc;
    }
    __syncthreads();

    for (int oy0 = 0; oy0 < 64; oy0 += 16) {
        for (int e = t; e < 43 * 138; e += 256) {
            int rr = e / 138, c = e - rr * 138;
            int rrow = 2 * oy0 + rr;
            if (rrow < 138) {
                int tp0 = (c + 1) & 1;
                float acc = 0.f;
                #pragma unroll
                for (int j = 0; j < 6; j++) {
                    int tp = tp0 + 2 * j;
                    int m = c + tp - 9;
                    if (m >= 0 && m <= 130) acc += sF[tp] * sUV[rrow * 68 + (m >> 1)];
                }
                float v = acc * 4.0f;
                v = (v >= 0.f ? v : 0.2f * v) * 1.4142135623730951f;
                v = fminf(fmaxf(v, -256.f), 256.f);
                sU[rr * 139 + c] = v;
            }
        }
        __syncthreads();
        for (int e = t; e < 16 * 138; e += 256) {
            int yy = e / 138, c = e - yy * 138;
            float acc = 0.f;
            #pragma unroll
            for (int tp = 0; tp < 12; tp++) acc += sF[12 + tp] * sU[(2 * yy + tp) * 139 + c];
            sDV[yy * 139 + c] = acc;
        }
        __syncthreads();
        for (int e = t; e < 16 * 64; e += 256) {
            int yy = e >> 6, ox = e & 63;
            float acc = 0.f;
            #pragma unroll
            for (int tp = 0; tp < 12; tp++) acc += sF[12 + tp] * sDV[yy * 139 + 2 * ox + tp];
            out[(size_t)nc * 4096 + (oy0 + yy) * 64 + ox] = acc;
        }
        __syncthreads();
    }
}

// ---------------- launch ----------------
extern "C" void kernel_launch(void* const* d_in, const int* in_sizes, int n_in,
                              void* d_out, int out_size) {
    const float* x  = (const float*)d_in[0];
    const float* w  = (const float*)d_in[1];
    const float* aw = (const float*)d_in[2];
    const float* ab = (const float*)d_in[3];
    const float* cw = (const float*)d_in[4];
    const float* cb = (const float*)d_in[5];
    const float* fu = (const float*)d_in[6];
    const float* fd = (const float*)d_in[7];
    float* out = (float*)d_out;

    cudaFuncSetAttribute(k_conv, cudaFuncAttributeMaxDynamicSharedMemorySize, CONV_SMEM);
    cudaFuncSetAttribute(k_fir,  cudaFuncAttributeMaxDynamicSharedMemorySize, FIR_SMEM);

    k_init<<<1, 1>>>();
    k_styles<<<NB, 512>>>(w, aw, ab);
    k_norm_s<<<NB, 512>>>();
    k_wt<<<CO, 512>>>(cw);
    k_d<<<(NB * CO) / 256, 256>>>();
    k_xsplit<<<dim3(68, NB), 256>>>(x);

    k_conv<<<dim3(4, 36, NB), 256, CONV_SMEM>>>(cb);

    k_fir<<<NB * CO, 256, FIR_SMEM>>>(fu, fd, out);
}

// round 8
// speedup vs baseline: 4.1641x; 1.3043x over previous
#include <cuda_runtime.h>
#include <cuda_fp16.h>
#include <cstdint>
#include <math.h>

#define NB 16
#define CI 512
#define CO 512
#define RES 64
#define YS 66
#define PSTR 4768
#define YPAD 4608
#define OS 64

// ---------------- scratch (device globals) ----------------
__device__ float g_styles[NB * CI];
__device__ float g_s[NB * CI];
__device__ float g_ssum[1];
__device__ float g_q[CO * CI];
__device__ float g_d[NB * CO];
__device__ __half g_wh[9 * CO * CI];            // [k9][o][i]
__device__ __half g_wl[9 * CO * CI];
__device__ __half g_xh[(size_t)NB * PSTR * CI]; // [n][p][i]
__device__ float g_y[(size_t)NB * CO * YPAD];

// ---------------- helpers ----------------
__device__ __forceinline__ uint32_t smem_u32(const void* p) {
    uint32_t a;
    asm("{ .reg .u64 t; cvta.to.shared.u64 t, %1; cvt.u32.u64 %0, t; }" : "=r"(a) : "l"(p));
    return a;
}
__device__ __forceinline__ void cp16(uint32_t dst, const void* src) {
    asm volatile("cp.async.cg.shared.global [%0], [%1], 16;" :: "r"(dst), "l"(src));
}
__device__ __forceinline__ void ldsm4(uint32_t* r, uint32_t addr) {
    asm volatile("ldmatrix.sync.aligned.m8n8.x4.shared.b16 {%0,%1,%2,%3}, [%4];"
                 : "=r"(r[0]), "=r"(r[1]), "=r"(r[2]), "=r"(r[3]) : "r"(addr));
}
__device__ __forceinline__ void mma16816(float* c, const uint32_t* a, uint32_t b0, uint32_t b1) {
    asm volatile(
        "mma.sync.aligned.m16n8k16.row.col.f32.f16.f16.f32 "
        "{%0,%1,%2,%3}, {%4,%5,%6,%7}, {%8,%9}, {%0,%1,%2,%3};"
        : "+f"(c[0]), "+f"(c[1]), "+f"(c[2]), "+f"(c[3])
        : "r"(a[0]), "r"(a[1]), "r"(a[2]), "r"(a[3]), "r"(b0), "r"(b1));
}

// ---------------- setup kernels ----------------
__global__ void k_init() { g_ssum[0] = 0.f; }

__global__ void k_styles(const float* __restrict__ w,
                         const float* __restrict__ aw,
                         const float* __restrict__ ab) {
    int n = blockIdx.x, c = threadIdx.x;
    const float* wr = w + n * 512;
    const float* ar = aw + c * 512;
    float acc = 0.f;
    #pragma unroll 8
    for (int k = 0; k < 512; k++) acc += wr[k] * ar[k];
    float st = acc * 0.044194173824159216f + ab[c];
    g_styles[n * CI + c] = st;
    float v = st * st;
    #pragma unroll
    for (int off = 16; off; off >>= 1) v += __shfl_down_sync(0xffffffffu, v, off);
    if ((threadIdx.x & 31) == 0) atomicAdd(g_ssum, v);
}

__global__ void k_norm_s() {
    int i = blockIdx.x * 512 + threadIdx.x;
    float msr = rsqrtf(g_ssum[0] * (1.0f / (NB * CI)));
    g_s[i] = g_styles[i] * msr;
}

__global__ void k_wt(const float* __restrict__ cw) {
    int o = blockIdx.x, i = threadIdx.x;
    float wl9[9]; float ss = 0.f;
    const float* p = cw + (o * CI + i) * 9;
    #pragma unroll
    for (int k = 0; k < 9; k++) { wl9[k] = p[k]; ss += wl9[k] * wl9[k]; }
    __shared__ float red[512];
    red[i] = ss;
    __syncthreads();
    for (int s = 256; s; s >>= 1) { if (i < s) red[i] += red[i + s]; __syncthreads(); }
    float inv = rsqrtf(red[0] * (1.0f / 4608.0f));
    #pragma unroll
    for (int k = 0; k < 9; k++) {
        float v = wl9[k] * inv;
        __half h = __float2half_rn(v);
        __half l = __float2half_rn(v - __half2float(h));
        g_wh[(k * 512 + o) * 512 + i] = h;
        g_wl[(k * 512 + o) * 512 + i] = l;
    }
    g_q[o * CI + i] = ss * inv * inv;
}

__global__ void k_d() {
    int idx = blockIdx.x * 256 + threadIdx.x;
    int n = idx & 15, o = idx >> 4;
    const float* sp = g_s + n * CI;
    const float* qp = g_q + o * CI;
    float acc = 0.f;
    #pragma unroll 4
    for (int i = 0; i < CI; i++) { float sv = sp[i]; acc += sv * sv * qp[i]; }
    g_d[n * CO + o] = rsqrtf(acc + 1e-8f);
}

// ---------------- x prep: modulate, pad to 68x68, channels-last, fp16
__global__ void __launch_bounds__(256) k_xsplit(const float* __restrict__ x) {
    int py = blockIdx.x, n = blockIdx.y, t = threadIdx.x;
    size_t obase = ((size_t)n * PSTR + (size_t)py * 68) * 512;
    int ys = py - 2;
    __half z = __float2half_rn(0.f);
    if (ys < 0 || ys >= 64) {
        for (int e = t; e < 68 * 512; e += 256) g_xh[obase + e] = z;
        return;
    }
    for (int e = t; e < 4 * 512; e += 256) {
        int col = e >> 9, i = e & 511;
        int px = (col < 2) ? col : (64 + col);
        g_xh[obase + (size_t)px * 512 + i] = z;
    }
    __shared__ float sh[64][65];
    const float* sp = g_s + n * 512;
    for (int i0 = 0; i0 < 512; i0 += 64) {
        __syncthreads();
        for (int e = t; e < 64 * 64; e += 256) {
            int ii = e >> 6, px = e & 63;
            sh[ii][px] = x[(((size_t)n * 512 + i0 + ii) * 64 + ys) * 64 + px] * sp[i0 + ii];
        }
        __syncthreads();
        for (int e = t; e < 64 * 64; e += 256) {
            int px = e >> 6, ii = e & 63;
            g_xh[obase + (size_t)(px + 2) * 512 + i0 + ii] = __float2half_rn(sh[ii][px]);
        }
    }
}

// ---------------- conv via mma.sync fp16 GEMM (2-term split) ----------------
// CTA: 128 oc x 128 px. Iter = (tap, ic-chunk-32): stage {Ah,Al,Bh}, 2 mma passes.
#define ROWB 80
#define TILEB 10240
#define STAGEB 30720
#define CONV_SMEM (2 * STAGEB)

__global__ void __launch_bounds__(256, 2) k_conv(const float* __restrict__ cb) {
    extern __shared__ char smem[];
    uint32_t sb = smem_u32(smem);
    int t = threadIdx.x, wid = t >> 5, lane = t & 31;
    int wm = wid & 1, wn = wid >> 1;
    int oc0 = blockIdx.x * 128;
    int p0  = blockIdx.y * 128;
    int n   = blockIdx.z;

    float acc[4][4][4];
    #pragma unroll
    for (int mi = 0; mi < 4; mi++)
        #pragma unroll
        for (int ni = 0; ni < 4; ni++)
            #pragma unroll
            for (int q = 0; q < 4; q++) acc[mi][ni][q] = 0.f;

    auto stage_issue = [&](int it, int buf) {
        int tap = it >> 4, icc = it & 15;
        int ic0 = icc << 5;
        int ky = tap / 3, kx = tap - ky * 3;
        const __half* ah = g_wh + ((size_t)(tap * 512 + oc0)) * 512 + ic0;
        const __half* al = g_wl + ((size_t)(tap * 512 + oc0)) * 512 + ic0;
        const __half* bh = g_xh + ((size_t)n * PSTR + p0 + ky * 68 + kx) * 512 + ic0;
        uint32_t sbase = sb + buf * STAGEB;
        #pragma unroll
        for (int j = 0; j < 6; j++) {
            int id = j * 256 + t;
            int tile = id >> 9, e = id & 511;
            int row = e >> 2, c16 = e & 3;
            const __half* src = (tile == 0) ? ah : (tile == 1) ? al : bh;
            cp16(sbase + tile * TILEB + row * ROWB + c16 * 16,
                 src + (size_t)row * 512 + c16 * 8);
        }
        asm volatile("cp.async.commit_group;" ::: "memory");
    };

    stage_issue(0, 0);

    int rl = lane & 15, chh = lane >> 4;
    for (int it = 0; it < 144; it++) {
        int buf = it & 1;
        if (it + 1 < 144) {
            stage_issue(it + 1, buf ^ 1);
            asm volatile("cp.async.wait_group 1;" ::: "memory");
        } else {
            asm volatile("cp.async.wait_group 0;" ::: "memory");
        }
        __syncthreads();

        uint32_t sbase = sb + buf * STAGEB;
        uint32_t Bt = sbase + 2 * TILEB;
        #pragma unroll
        for (int kk = 0; kk < 2; kk++) {
            uint32_t b[2][4];
            #pragma unroll
            for (int nj = 0; nj < 2; nj++)
                ldsm4(b[nj], Bt + (wn * 32 + nj * 16 + rl) * ROWB + (kk * 2 + chh) * 16);
            #pragma unroll
            for (int pass = 0; pass < 2; pass++) {
                uint32_t At = sbase + pass * TILEB;
                uint32_t a[4][4];
                #pragma unroll
                for (int mi = 0; mi < 4; mi++)
                    ldsm4(a[mi], At + (wm * 64 + mi * 16 + rl) * ROWB + (kk * 2 + chh) * 16);
                #pragma unroll
                for (int mi = 0; mi < 4; mi++)
                    #pragma unroll
                    for (int ni = 0; ni < 4; ni++) {
                        int nj = ni >> 1, sub = ni & 1;
                        mma16816(acc[mi][ni], a[mi], b[nj][sub], b[nj][sub + 2]);
                    }
            }
        }
        __syncthreads();
    }

    // ---- epilogue: demod + bias, write g_y ----
    int g4 = lane >> 2, t4 = lane & 3;
    #pragma unroll
    for (int mi = 0; mi < 4; mi++) {
        int oc_a = oc0 + wm * 64 + mi * 16 + g4;
        int oc_b = oc_a + 8;
        float da = g_d[n * CO + oc_a], ba = cb[oc_a];
        float db = g_d[n * CO + oc_b], bb = cb[oc_b];
        float* ya = g_y + ((size_t)(n * CO + oc_a)) * YPAD + p0;
        float* yb = g_y + ((size_t)(n * CO + oc_b)) * YPAD + p0;
        #pragma unroll
        for (int ni = 0; ni < 4; ni++) {
            int px = wn * 32 + ni * 8 + t4 * 2;
            float2 va, vb;
            va.x = acc[mi][ni][0] * da + ba;
            va.y = acc[mi][ni][1] * da + ba;
            vb.x = acc[mi][ni][2] * db + bb;
            vb.y = acc[mi][ni][3] * db + bb;
            *(float2*)(ya + px) = va;
            *(float2*)(yb + px) = vb;
        }
    }
}

// ---------------- fused filtered_lrelu: one CTA per (n,c) image ----------------
#define F_SY 0
#define F_SUV 4488
#define F_SU (4488 + 9384)
#define F_SDV (13872 + 5977)
#define F_SF (19849 + 2224)
#define FIR_SMEM ((22073 + 24) * 4)

__global__ void __launch_bounds__(256, 2) k_fir(const float* __restrict__ fu,
                                                const float* __restrict__ fd,
                                                float* __restrict__ out) {
    extern __shared__ float sm[];
    float* sY  = sm + F_SY;
    float* sUV = sm + F_SUV;
    float* sU  = sm + F_SU;
    float* sDV = sm + F_SDV;
    float* sF  = sm + F_SF;
    int t = threadIdx.x;
    int nc = blockIdx.x;

    if (t < 12) sF[t] = fu[t];
    else if (t < 24) sF[t] = fd[t - 12];
    const float4* gy = (const float4*)(g_y + (size_t)nc * YPAD);
    float4* sY4 = (float4*)sY;
    for (int e = t; e < 1122; e += 256) sY4[e] = gy[e];
    __syncthreads();

    for (int e = t; e < 138 * 66; e += 256) {
        int r = e / 66, xx = e - r * 66;
        int tp0 = (r + 1) & 1;
        float acc = 0.f;
        #pragma unroll
        for (int j = 0; j < 6; j++) {
            int tp = tp0 + 2 * j;
            int m = r + tp - 9;
            if (m >= 0 && m <= 130) acc += sF[tp] * sY[(m >> 1) * 68 + xx];
        }
        sUV[r * 68 + xx] = acc;
    }
    __syncthreads();

    for (int oy0 = 0; oy0 < 64; oy0 += 16) {
        for (int e = t; e < 43 * 138; e += 256) {
            int rr = e / 138, c = e - rr * 138;
            int rrow = 2 * oy0 + rr;
            if (rrow < 138) {
                int tp0 = (c + 1) & 1;
                float acc = 0.f;
                #pragma unroll
                for (int j = 0; j < 6; j++) {
                    int tp = tp0 + 2 * j;
                    int m = c + tp - 9;
                    if (m >= 0 && m <= 130) acc += sF[tp] * sUV[rrow * 68 + (m >> 1)];
                }
                float v = acc * 4.0f;
                v = (v >= 0.f ? v : 0.2f * v) * 1.4142135623730951f;
                v = fminf(fmaxf(v, -256.f), 256.f);
                sU[rr * 139 + c] = v;
            }
        }
        __syncthreads();
        for (int e = t; e < 16 * 138; e += 256) {
            int yy = e / 138, c = e - yy * 138;
            float acc = 0.f;
            #pragma unroll
            for (int tp = 0; tp < 12; tp++) acc += sF[12 + tp] * sU[(2 * yy + tp) * 139 + c];
            sDV[yy * 139 + c] = acc;
        }
        __syncthreads();
        for (int e = t; e < 16 * 64; e += 256) {
            int yy = e >> 6, ox = e & 63;
            float acc = 0.f;
            #pragma unroll
            for (int tp = 0; tp < 12; tp++) acc += sF[12 + tp] * sDV[yy * 139 + 2 * ox + tp];
            out[(size_t)nc * 4096 + (oy0 + yy) * 64 + ox] = acc;
        }
        __syncthreads();
    }
}

// ---------------- launch ----------------
extern "C" void kernel_launch(void* const* d_in, const int* in_sizes, int n_in,
                              void* d_out, int out_size) {
    const float* x  = (const float*)d_in[0];
    const float* w  = (const float*)d_in[1];
    const float* aw = (const float*)d_in[2];
    const float* ab = (const float*)d_in[3];
    const float* cw = (const float*)d_in[4];
    const float* cb = (const float*)d_in[5];
    const float* fu = (const float*)d_in[6];
    const float* fd = (const float*)d_in[7];
    float* out = (float*)d_out;

    cudaFuncSetAttribute(k_conv, cudaFuncAttributeMaxDynamicSharedMemorySize, CONV_SMEM);
    cudaFuncSetAttribute(k_fir,  cudaFuncAttributeMaxDynamicSharedMemorySize, FIR_SMEM);

    k_init<<<1, 1>>>();
    k_styles<<<NB, 512>>>(w, aw, ab);
    k_norm_s<<<NB, 512>>>();
    k_wt<<<CO, 512>>>(cw);
    k_d<<<(NB * CO) / 256, 256>>>();
    k_xsplit<<<dim3(68, NB), 256>>>(x);

    k_conv<<<dim3(4, 36, NB), 256, CONV_SMEM>>>(cb);

    k_fir<<<NB * CO, 256, FIR_SMEM>>>(fu, fd, out);
}

// round 10
// speedup vs baseline: 6.1063x; 1.4664x over previous
#include <cuda_runtime.h>
#include <cuda_fp16.h>
#include <cstdint>
#include <math.h>

#define NB 16
#define CI 512
#define CO 512
#define RES 64
#define YS 66
#define PSTR 4768
#define YPAD 4608
#define OS 64

// ---------------- scratch (device globals) ----------------
__device__ float g_styles[NB * CI];
__device__ float g_s[NB * CI];
__device__ float g_ssum[1];
__device__ float g_q[CO * CI];
__device__ float g_d[NB * CO];
__device__ __half g_wh[9 * CO * CI];            // [k9][o][i]
__device__ __half g_xh[(size_t)NB * PSTR * CI]; // [n][p][i]
__device__ float g_y[(size_t)NB * CO * YPAD];

// ---------------- helpers ----------------
__device__ __forceinline__ uint32_t smem_u32(const void* p) {
    uint32_t a;
    asm("{ .reg .u64 t; cvta.to.shared.u64 t, %1; cvt.u32.u64 %0, t; }" : "=r"(a) : "l"(p));
    return a;
}
__device__ __forceinline__ void cp16(uint32_t dst, const void* src) {
    asm volatile("cp.async.cg.shared.global [%0], [%1], 16;" :: "r"(dst), "l"(src));
}
__device__ __forceinline__ void ldsm4(uint32_t* r, uint32_t addr) {
    asm volatile("ldmatrix.sync.aligned.m8n8.x4.shared.b16 {%0,%1,%2,%3}, [%4];"
                 : "=r"(r[0]), "=r"(r[1]), "=r"(r[2]), "=r"(r[3]) : "r"(addr));
}
__device__ __forceinline__ void mma16816(float* c, const uint32_t* a, uint32_t b0, uint32_t b1) {
    asm volatile(
        "mma.sync.aligned.m16n8k16.row.col.f32.f16.f16.f32 "
        "{%0,%1,%2,%3}, {%4,%5,%6,%7}, {%8,%9}, {%0,%1,%2,%3};"
        : "+f"(c[0]), "+f"(c[1]), "+f"(c[2]), "+f"(c[3])
        : "r"(a[0]), "r"(a[1]), "r"(a[2]), "r"(a[3]), "r"(b0), "r"(b1));
}

// ---------------- setup kernels ----------------
__global__ void k_init() { g_ssum[0] = 0.f; }

__global__ void k_styles(const float* __restrict__ w,
                         const float* __restrict__ aw,
                         const float* __restrict__ ab) {
    int n = blockIdx.x, c = threadIdx.x;
    const float* wr = w + n * 512;
    const float* ar = aw + c * 512;
    float acc = 0.f;
    #pragma unroll 8
    for (int k = 0; k < 512; k++) acc += wr[k] * ar[k];
    float st = acc * 0.044194173824159216f + ab[c];
    g_styles[n * CI + c] = st;
    float v = st * st;
    #pragma unroll
    for (int off = 16; off; off >>= 1) v += __shfl_down_sync(0xffffffffu, v, off);
    if ((threadIdx.x & 31) == 0) atomicAdd(g_ssum, v);
}

__global__ void k_norm_s() {
    int i = blockIdx.x * 512 + threadIdx.x;
    float msr = rsqrtf(g_ssum[0] * (1.0f / (NB * CI)));
    g_s[i] = g_styles[i] * msr;
}

__global__ void k_wt(const float* __restrict__ cw) {
    int o = blockIdx.x, i = threadIdx.x;
    float wl9[9]; float ss = 0.f;
    const float* p = cw + (o * CI + i) * 9;
    #pragma unroll
    for (int k = 0; k < 9; k++) { wl9[k] = p[k]; ss += wl9[k] * wl9[k]; }
    __shared__ float red[512];
    red[i] = ss;
    __syncthreads();
    for (int s = 256; s; s >>= 1) { if (i < s) red[i] += red[i + s]; __syncthreads(); }
    float inv = rsqrtf(red[0] * (1.0f / 4608.0f));
    #pragma unroll
    for (int k = 0; k < 9; k++)
        g_wh[(k * 512 + o) * 512 + i] = __float2half_rn(wl9[k] * inv);
    g_q[o * CI + i] = ss * inv * inv;
}

__global__ void k_d() {
    int idx = blockIdx.x * 256 + threadIdx.x;
    int n = idx & 15, o = idx >> 4;
    const float* sp = g_s + n * CI;
    const float* qp = g_q + o * CI;
    float acc = 0.f;
    #pragma unroll 4
    for (int i = 0; i < CI; i++) { float sv = sp[i]; acc += sv * sv * qp[i]; }
    g_d[n * CO + o] = rsqrtf(acc + 1e-8f);
}

// ---------------- x prep: modulate, pad to 68x68, channels-last, fp16
__global__ void __launch_bounds__(256) k_xsplit(const float* __restrict__ x) {
    int py = blockIdx.x, n = blockIdx.y, t = threadIdx.x;
    size_t obase = ((size_t)n * PSTR + (size_t)py * 68) * 512;
    int ys = py - 2;
    __half z = __float2half_rn(0.f);
    if (ys < 0 || ys >= 64) {
        for (int e = t; e < 68 * 512; e += 256) g_xh[obase + e] = z;
        return;
    }
    for (int e = t; e < 4 * 512; e += 256) {
        int col = e >> 9, i = e & 511;
        int px = (col < 2) ? col : (64 + col);
        g_xh[obase + (size_t)px * 512 + i] = z;
    }
    __shared__ float sh[64][65];
    const float* sp = g_s + n * 512;
    for (int i0 = 0; i0 < 512; i0 += 64) {
        __syncthreads();
        for (int e = t; e < 64 * 64; e += 256) {
            int ii = e >> 6, px = e & 63;
            sh[ii][px] = x[(((size_t)n * 512 + i0 + ii) * 64 + ys) * 64 + px] * sp[i0 + ii];
        }
        __syncthreads();
        for (int e = t; e < 64 * 64; e += 256) {
            int px = e >> 6, ii = e & 63;
            g_xh[obase + (size_t)(px + 2) * 512 + i0 + ii] = __float2half_rn(sh[ii][px]);
        }
    }
}

// ---------------- conv via mma.sync fp16 GEMM (single pass) ----------------
// CTA: 128 oc x 128 px. Iter = (tap, ic-chunk-64): stage {A, B}, 4 kk steps.
#define ROWB 144
#define TILEB 18432
#define STAGEB 36864
#define CONV_SMEM (2 * STAGEB)

__global__ void __launch_bounds__(256, 2) k_conv(const float* __restrict__ cb) {
    extern __shared__ char smem[];
    uint32_t sb = smem_u32(smem);
    int t = threadIdx.x, wid = t >> 5, lane = t & 31;
    int wm = wid & 1, wn = wid >> 1;
    int oc0 = blockIdx.x * 128;
    int p0  = blockIdx.y * 128;
    int n   = blockIdx.z;

    float acc[4][4][4];
    #pragma unroll
    for (int mi = 0; mi < 4; mi++)
        #pragma unroll
        for (int ni = 0; ni < 4; ni++)
            #pragma unroll
            for (int q = 0; q < 4; q++) acc[mi][ni][q] = 0.f;

    auto stage_issue = [&](int it, int buf) {
        int tap = it >> 3, icc = it & 7;
        int ic0 = icc << 6;
        int ky = tap / 3, kx = tap - ky * 3;
        const __half* ah = g_wh + ((size_t)(tap * 512 + oc0)) * 512 + ic0;
        const __half* bh = g_xh + ((size_t)n * PSTR + p0 + ky * 68 + kx) * 512 + ic0;
        uint32_t sbase = sb + buf * STAGEB;
        #pragma unroll
        for (int j = 0; j < 8; j++) {
            int id = j * 256 + t;
            int tile = id >> 10, e = id & 1023;
            int row = e >> 3, c16 = e & 7;
            const __half* src = tile ? bh : ah;
            cp16(sbase + tile * TILEB + row * ROWB + c16 * 16,
                 src + (size_t)row * 512 + c16 * 8);
        }
        asm volatile("cp.async.commit_group;" ::: "memory");
    };

    stage_issue(0, 0);

    int rl = lane & 15, chh = lane >> 4;
    for (int it = 0; it < 72; it++) {
        int buf = it & 1;
        if (it + 1 < 72) {
            stage_issue(it + 1, buf ^ 1);
            asm volatile("cp.async.wait_group 1;" ::: "memory");
        } else {
            asm volatile("cp.async.wait_group 0;" ::: "memory");
        }
        __syncthreads();

        uint32_t At = sb + buf * STAGEB;
        uint32_t Bt = At + TILEB;
        #pragma unroll
        for (int kk = 0; kk < 4; kk++) {
            uint32_t kb = (kk * 2 + chh) * 16;
            uint32_t a[4][4], b[2][4];
            #pragma unroll
            for (int nj = 0; nj < 2; nj++)
                ldsm4(b[nj], Bt + (wn * 32 + nj * 16 + rl) * ROWB + kb);
            #pragma unroll
            for (int mi = 0; mi < 4; mi++)
                ldsm4(a[mi], At + (wm * 64 + mi * 16 + rl) * ROWB + kb);
            #pragma unroll
            for (int mi = 0; mi < 4; mi++)
                #pragma unroll
                for (int ni = 0; ni < 4; ni++) {
                    int nj = ni >> 1, sub = ni & 1;
                    mma16816(acc[mi][ni], a[mi], b[nj][sub], b[nj][sub + 2]);
                }
        }
        __syncthreads();
    }

    // ---- epilogue: demod + bias, write g_y ----
    int g4 = lane >> 2, t4 = lane & 3;
    #pragma unroll
    for (int mi = 0; mi < 4; mi++) {
        int oc_a = oc0 + wm * 64 + mi * 16 + g4;
        int oc_b = oc_a + 8;
        float da = g_d[n * CO + oc_a], ba = cb[oc_a];
        float db = g_d[n * CO + oc_b], bb = cb[oc_b];
        float* ya = g_y + ((size_t)(n * CO + oc_a)) * YPAD + p0;
        float* yb = g_y + ((size_t)(n * CO + oc_b)) * YPAD + p0;
        #pragma unroll
        for (int ni = 0; ni < 4; ni++) {
            int px = wn * 32 + ni * 8 + t4 * 2;
            float2 va, vb;
            va.x = acc[mi][ni][0] * da + ba;
            va.y = acc[mi][ni][1] * da + ba;
            vb.x = acc[mi][ni][2] * db + bb;
            vb.y = acc[mi][ni][3] * db + bb;
            *(float2*)(ya + px) = va;
            *(float2*)(yb + px) = vb;
        }
    }
}

// ---------------- fused filtered_lrelu: one CTA per (n,c) image ----------------
#define F_SY 0
#define F_SUV 4488
#define F_SU (4488 + 9384)
#define F_SDV (13872 + 5977)
#define F_SF (19849 + 2224)
#define FIR_SMEM ((22073 + 24) * 4)

__global__ void __launch_bounds__(256, 2) k_fir(const float* __restrict__ fu,
                                                const float* __restrict__ fd,
                                                float* __restrict__ out) {
    extern __shared__ float sm[];
    float* sY  = sm + F_SY;
    float* sUV = sm + F_SUV;
    float* sU  = sm + F_SU;
    float* sDV = sm + F_SDV;
    float* sF  = sm + F_SF;
    int t = threadIdx.x;
    int nc = blockIdx.x;

    if (t < 12) sF[t] = fu[t];
    else if (t < 24) sF[t] = fd[t - 12];
    const float4* gy = (const float4*)(g_y + (size_t)nc * YPAD);
    float4* sY4 = (float4*)sY;
    for (int e = t; e < 1122; e += 256) sY4[e] = gy[e];
    __syncthreads();

    for (int e = t; e < 138 * 66; e += 256) {
        int r = e / 66, xx = e - r * 66;
        int tp0 = (r + 1) & 1;
        float acc = 0.f;
        #pragma unroll
        for (int j = 0; j < 6; j++) {
            int tp = tp0 + 2 * j;
            int m = r + tp - 9;
            if (m >= 0 && m <= 130) acc += sF[tp] * sY[(m >> 1) * 68 + xx];
        }
        sUV[r * 68 + xx] = acc;
    }
    __syncthreads();

    for (int oy0 = 0; oy0 < 64; oy0 += 16) {
        for (int e = t; e < 43 * 138; e += 256) {
            int rr = e / 138, c = e - rr * 138;
            int rrow = 2 * oy0 + rr;
            if (rrow < 138) {
                int tp0 = (c + 1) & 1;
                float acc = 0.f;
                #pragma unroll
                for (int j = 0; j < 6; j++) {
                    int tp = tp0 + 2 * j;
                    int m = c + tp - 9;
                    if (m >= 0 && m <= 130) acc += sF[tp] * sUV[rrow * 68 + (m >> 1)];
                }
                float v = acc * 4.0f;
                v = (v >= 0.f ? v : 0.2f * v) * 1.4142135623730951f;
                v = fminf(fmaxf(v, -256.f), 256.f);
                sU[rr * 139 + c] = v;
            }
        }
        __syncthreads();
        for (int e = t; e < 16 * 138; e += 256) {
            int yy = e / 138, c = e - yy * 138;
            float acc = 0.f;
            #pragma unroll
            for (int tp = 0; tp < 12; tp++) acc += sF[12 + tp] * sU[(2 * yy + tp) * 139 + c];
            sDV[yy * 139 + c] = acc;
        }
        __syncthreads();
        for (int e = t; e < 16 * 64; e += 256) {
            int yy = e >> 6, ox = e & 63;
            float acc = 0.f;
            #pragma unroll
            for (int tp = 0; tp < 12; tp++) acc += sF[12 + tp] * sDV[yy * 139 + 2 * ox + tp];
            out[(size_t)nc * 4096 + (oy0 + yy) * 64 + ox] = acc;
        }
        __syncthreads();
    }
}

// ---------------- launch ----------------
extern "C" void kernel_launch(void* const* d_in, const int* in_sizes, int n_in,
                              void* d_out, int out_size) {
    const float* x  = (const float*)d_in[0];
    const float* w  = (const float*)d_in[1];
    const float* aw = (const float*)d_in[2];
    const float* ab = (const float*)d_in[3];
    const float* cw = (const float*)d_in[4];
    const float* cb = (const float*)d_in[5];
    const float* fu = (const float*)d_in[6];
    const float* fd = (const float*)d_in[7];
    float* out = (float*)d_out;

    cudaFuncSetAttribute(k_conv, cudaFuncAttributeMaxDynamicSharedMemorySize, CONV_SMEM);
    cudaFuncSetAttribute(k_fir,  cudaFuncAttributeMaxDynamicSharedMemorySize, FIR_SMEM);

    k_init<<<1, 1>>>();
    k_styles<<<NB, 512>>>(w, aw, ab);
    k_norm_s<<<NB, 512>>>();
    k_wt<<<CO, 512>>>(cw);
    k_d<<<(NB * CO) / 256, 256>>>();
    k_xsplit<<<dim3(68, NB), 256>>>(x);

    k_conv<<<dim3(4, 36, NB), 256, CONV_SMEM>>>(cb);

    k_fir<<<NB * CO, 256, FIR_SMEM>>>(fu, fd, out);
}

// round 11
// speedup vs baseline: 7.9388x; 1.3001x over previous
#include <cuda_runtime.h>
#include <cuda_fp16.h>
#include <cstdint>
#include <math.h>

#define NB 16
#define CI 512
#define CO 512
#define RES 64
#define YS 66
#define PSTR 4768
#define YPAD 4608
#define OS 64

// ---------------- scratch (device globals) ----------------
__device__ float g_styles[NB * CI];
__device__ float g_s[NB * CI];
__device__ float g_ssum16[NB];
__device__ float g_q[CO * CI];
__device__ float g_d[NB * CO];
__device__ __half g_wh[9 * CO * CI];            // [k9][o][i]
__device__ __half g_xh[(size_t)NB * PSTR * CI]; // [n][p][i]
__device__ float g_y[(size_t)NB * CO * YPAD];

// ---------------- helpers ----------------
__device__ __forceinline__ uint32_t smem_u32(const void* p) {
    uint32_t a;
    asm("{ .reg .u64 t; cvta.to.shared.u64 t, %1; cvt.u32.u64 %0, t; }" : "=r"(a) : "l"(p));
    return a;
}
__device__ __forceinline__ void cp16(uint32_t dst, const void* src) {
    asm volatile("cp.async.cg.shared.global [%0], [%1], 16;" :: "r"(dst), "l"(src));
}
__device__ __forceinline__ void ldsm4(uint32_t* r, uint32_t addr) {
    asm volatile("ldmatrix.sync.aligned.m8n8.x4.shared.b16 {%0,%1,%2,%3}, [%4];"
                 : "=r"(r[0]), "=r"(r[1]), "=r"(r[2]), "=r"(r[3]) : "r"(addr));
}
__device__ __forceinline__ void mma16816(float* c, const uint32_t* a, uint32_t b0, uint32_t b1) {
    asm volatile(
        "mma.sync.aligned.m16n8k16.row.col.f32.f16.f16.f32 "
        "{%0,%1,%2,%3}, {%4,%5,%6,%7}, {%8,%9}, {%0,%1,%2,%3};"
        : "+f"(c[0]), "+f"(c[1]), "+f"(c[2]), "+f"(c[3])
        : "r"(a[0]), "r"(a[1]), "r"(a[2]), "r"(a[3]), "r"(b0), "r"(b1));
}

// ---------------- setup kernels ----------------
__global__ void k_styles(const float* __restrict__ w,
                         const float* __restrict__ aw,
                         const float* __restrict__ ab) {
    int n = blockIdx.x, c = threadIdx.x;
    const float* wr = w + n * 512;
    const float* ar = aw + c * 512;
    float acc = 0.f;
    #pragma unroll 8
    for (int k = 0; k < 512; k++) acc += wr[k] * ar[k];
    float st = acc * 0.044194173824159216f + ab[c];
    g_styles[n * CI + c] = st;
    float v = st * st;
    #pragma unroll
    for (int off = 16; off; off >>= 1) v += __shfl_down_sync(0xffffffffu, v, off);
    __shared__ float ps[16];
    if ((c & 31) == 0) ps[c >> 5] = v;
    __syncthreads();
    if (c == 0) {
        float tot = 0.f;
        #pragma unroll
        for (int k = 0; k < 16; k++) tot += ps[k];
        g_ssum16[n] = tot;
    }
}

__global__ void k_norm_s() {
    int i = blockIdx.x * 512 + threadIdx.x;
    float tot = 0.f;
    #pragma unroll
    for (int k = 0; k < NB; k++) tot += g_ssum16[k];
    float msr = rsqrtf(tot * (1.0f / (NB * CI)));
    g_s[i] = g_styles[i] * msr;
}

__global__ void k_wt(const float* __restrict__ cw) {
    int o = blockIdx.x, i = threadIdx.x;
    float wl9[9]; float ss = 0.f;
    const float* p = cw + (o * CI + i) * 9;
    #pragma unroll
    for (int k = 0; k < 9; k++) { wl9[k] = p[k]; ss += wl9[k] * wl9[k]; }
    __shared__ float red[512];
    red[i] = ss;
    __syncthreads();
    for (int s = 256; s; s >>= 1) { if (i < s) red[i] += red[i + s]; __syncthreads(); }
    float inv = rsqrtf(red[0] * (1.0f / 4608.0f));
    #pragma unroll
    for (int k = 0; k < 9; k++)
        g_wh[(k * 512 + o) * 512 + i] = __float2half_rn(wl9[k] * inv);
    g_q[o * CI + i] = ss * inv * inv;
}

__global__ void k_d() {
    int idx = blockIdx.x * 256 + threadIdx.x;
    int n = idx & 15, o = idx >> 4;
    const float* sp = g_s + n * CI;
    const float* qp = g_q + o * CI;
    float acc = 0.f;
    #pragma unroll 4
    for (int i = 0; i < CI; i++) { float sv = sp[i]; acc += sv * sv * qp[i]; }
    g_d[n * CO + o] = rsqrtf(acc + 1e-8f);
}

// ---------------- x prep: modulate, pad to 68x68, channels-last, fp16
__global__ void __launch_bounds__(256) k_xsplit(const float* __restrict__ x) {
    int py = blockIdx.x, n = blockIdx.y, t = threadIdx.x;
    size_t obase = ((size_t)n * PSTR + (size_t)py * 68) * 512;
    int ys = py - 2;
    __half z = __float2half_rn(0.f);
    if (ys < 0 || ys >= 64) {
        for (int e = t; e < 68 * 512; e += 256) g_xh[obase + e] = z;
        return;
    }
    for (int e = t; e < 4 * 512; e += 256) {
        int col = e >> 9, i = e & 511;
        int px = (col < 2) ? col : (64 + col);
        g_xh[obase + (size_t)px * 512 + i] = z;
    }
    __shared__ float sh[64][65];
    const float* sp = g_s + n * 512;
    for (int i0 = 0; i0 < 512; i0 += 64) {
        __syncthreads();
        for (int e = t; e < 64 * 64; e += 256) {
            int ii = e >> 6, px = e & 63;
            sh[ii][px] = x[(((size_t)n * 512 + i0 + ii) * 64 + ys) * 64 + px] * sp[i0 + ii];
        }
        __syncthreads();
        for (int e = t; e < 64 * 64; e += 256) {
            int px = e >> 6, ii = e & 63;
            g_xh[obase + (size_t)(px + 2) * 512 + i0 + ii] = __float2half_rn(sh[ii][px]);
        }
    }
}

// ---------------- conv via mma.sync fp16 GEMM (single pass) ----------------
#define ROWB 144
#define TILEB 18432
#define STAGEB 36864
#define CONV_SMEM (2 * STAGEB)

__global__ void __launch_bounds__(256, 2) k_conv(const float* __restrict__ cb) {
    extern __shared__ char smem[];
    uint32_t sb = smem_u32(smem);
    int t = threadIdx.x, wid = t >> 5, lane = t & 31;
    int wm = wid & 1, wn = wid >> 1;
    int oc0 = blockIdx.x * 128;
    int p0  = blockIdx.y * 128;
    int n   = blockIdx.z;

    float acc[4][4][4];
    #pragma unroll
    for (int mi = 0; mi < 4; mi++)
        #pragma unroll
        for (int ni = 0; ni < 4; ni++)
            #pragma unroll
            for (int q = 0; q < 4; q++) acc[mi][ni][q] = 0.f;

    auto stage_issue = [&](int it, int buf) {
        int tap = it >> 3, icc = it & 7;
        int ic0 = icc << 6;
        int ky = tap / 3, kx = tap - ky * 3;
        const __half* ah = g_wh + ((size_t)(tap * 512 + oc0)) * 512 + ic0;
        const __half* bh = g_xh + ((size_t)n * PSTR + p0 + ky * 68 + kx) * 512 + ic0;
        uint32_t sbase = sb + buf * STAGEB;
        #pragma unroll
        for (int j = 0; j < 8; j++) {
            int id = j * 256 + t;
            int tile = id >> 10, e = id & 1023;
            int row = e >> 3, c16 = e & 7;
            const __half* src = tile ? bh : ah;
            cp16(sbase + tile * TILEB + row * ROWB + c16 * 16,
                 src + (size_t)row * 512 + c16 * 8);
        }
        asm volatile("cp.async.commit_group;" ::: "memory");
    };

    stage_issue(0, 0);

    int rl = lane & 15, chh = lane >> 4;
    for (int it = 0; it < 72; it++) {
        int buf = it & 1;
        if (it + 1 < 72) {
            stage_issue(it + 1, buf ^ 1);
            asm volatile("cp.async.wait_group 1;" ::: "memory");
        } else {
            asm volatile("cp.async.wait_group 0;" ::: "memory");
        }
        __syncthreads();

        uint32_t At = sb + buf * STAGEB;
        uint32_t Bt = At + TILEB;
        #pragma unroll
        for (int kk = 0; kk < 4; kk++) {
            uint32_t kb = (kk * 2 + chh) * 16;
            uint32_t a[4][4], b[2][4];
            #pragma unroll
            for (int nj = 0; nj < 2; nj++)
                ldsm4(b[nj], Bt + (wn * 32 + nj * 16 + rl) * ROWB + kb);
            #pragma unroll
            for (int mi = 0; mi < 4; mi++)
                ldsm4(a[mi], At + (wm * 64 + mi * 16 + rl) * ROWB + kb);
            #pragma unroll
            for (int mi = 0; mi < 4; mi++)
                #pragma unroll
                for (int ni = 0; ni < 4; ni++) {
                    int nj = ni >> 1, sub = ni & 1;
                    mma16816(acc[mi][ni], a[mi], b[nj][sub], b[nj][sub + 2]);
                }
        }
        __syncthreads();
    }

    int g4 = lane >> 2, t4 = lane & 3;
    #pragma unroll
    for (int mi = 0; mi < 4; mi++) {
        int oc_a = oc0 + wm * 64 + mi * 16 + g4;
        int oc_b = oc_a + 8;
        float da = g_d[n * CO + oc_a], ba = cb[oc_a];
        float db = g_d[n * CO + oc_b], bb = cb[oc_b];
        float* ya = g_y + ((size_t)(n * CO + oc_a)) * YPAD + p0;
        float* yb = g_y + ((size_t)(n * CO + oc_b)) * YPAD + p0;
        #pragma unroll
        for (int ni = 0; ni < 4; ni++) {
            int px = wn * 32 + ni * 8 + t4 * 2;
            float2 va, vb;
            va.x = acc[mi][ni][0] * da + ba;
            va.y = acc[mi][ni][1] * da + ba;
            vb.x = acc[mi][ni][2] * db + bb;
            vb.y = acc[mi][ni][3] * db + bb;
            *(float2*)(ya + px) = va;
            *(float2*)(yb + px) = vb;
        }
    }
}

// ---------------- fused filtered_lrelu (optimized): one CTA per (n,c) ----------------
// sY: 74 rows x 68 (rows 0-3, 70-73 zero; rows 4..69 = y rows 0..65)
// sUV: 138 rows x stride 76 (cols 0-3, 70-73 zero; cols 4..69 = uv cols 0..65)
// sU: 42 rows x stride 139; sDV: 16 x 139
#define F_SY 0
#define F_SUV 5032
#define F_SU 15520
#define F_SDV 21358
#define FIR_SMEM (23582 * 4)
#define LRC1 5.656854249492381f   // 4*sqrt(2)
#define LRC2 1.1313708498984762f  // 0.8*sqrt(2)

__global__ void __launch_bounds__(256, 2) k_fir(const float* __restrict__ fu,
                                                const float* __restrict__ fd,
                                                float* __restrict__ out) {
    extern __shared__ float sm[];
    float* sY  = sm + F_SY;
    float* sUV = sm + F_SUV;
    float* sU  = sm + F_SU;
    float* sDV = sm + F_SDV;
    int t = threadIdx.x;
    int nc = blockIdx.x;

    float fe[6], fo[6], fdr[12];
    #pragma unroll
    for (int j = 0; j < 6; j++) { fe[j] = fu[2 * j]; fo[j] = fu[2 * j + 1]; }
    #pragma unroll
    for (int j = 0; j < 12; j++) fdr[j] = fd[j];

    // load y into padded sY; zero pad rows
    float4* sY4 = (float4*)sY;
    const float4* gy = (const float4*)(g_y + (size_t)nc * YPAD);
    for (int e = t; e < 1122; e += 256) sY4[68 + e] = gy[e];
    float4 z4 = make_float4(0.f, 0.f, 0.f, 0.f);
    for (int e = t; e < 136; e += 256) sY4[(e < 68) ? e : (1122 + e)] = z4;
    // zero sUV pad cols
    for (int e = t; e < 138 * 8; e += 256) {
        int r = e >> 3, c = e & 7;
        sUV[r * 76 + ((c < 4) ? c : (66 + c))] = 0.f;
    }
    __syncthreads();

    // up-vertical, paired parity: rows 2q (odd taps) and 2q+1 (even taps) share sources
    for (int e = t; e < 69 * 66; e += 256) {
        int q = e / 66, xx = e - q * 66;
        const float* src = sY + q * 68 + xx;
        float ve = 0.f, vo = 0.f;
        #pragma unroll
        for (int j = 0; j < 6; j++) {
            float s = src[j * 68];
            ve += fo[j] * s;   // row 2q
            vo += fe[j] * s;   // row 2q+1
        }
        sUV[(2 * q) * 76 + 4 + xx] = ve;
        sUV[(2 * q + 1) * 76 + 4 + xx] = vo;
    }
    __syncthreads();

    for (int oy0 = 0; oy0 < 64; oy0 += 16) {
        // up-horizontal + lrelu + clamp: cols 2q / 2q+1 share sources
        for (int e = t; e < 42 * 69; e += 256) {
            int rr = e / 69, q = e - rr * 69;
            const float* src = sUV + (2 * oy0 + rr) * 76 + q;
            float ve = 0.f, vo = 0.f;
            #pragma unroll
            for (int j = 0; j < 6; j++) {
                float s = src[j];
                ve += fo[j] * s;
                vo += fe[j] * s;
            }
            float w0 = fminf(fmaxf(fmaxf(ve * LRC1, ve * LRC2), -256.f), 256.f);
            float w1 = fminf(fmaxf(fmaxf(vo * LRC1, vo * LRC2), -256.f), 256.f);
            sU[rr * 139 + 2 * q] = w0;
            sU[rr * 139 + 2 * q + 1] = w1;
        }
        __syncthreads();
        // down-vertical
        for (int e = t; e < 16 * 138; e += 256) {
            int yy = e / 138, c = e - yy * 138;
            const float* src = sU + 2 * yy * 139 + c;
            float acc = 0.f;
            #pragma unroll
            for (int tp = 0; tp < 12; tp++) acc += fdr[tp] * src[tp * 139];
            sDV[yy * 139 + c] = acc;
        }
        __syncthreads();
        // down-horizontal -> out
        for (int e = t; e < 16 * 64; e += 256) {
            int yy = e >> 6, ox = e & 63;
            const float* src = sDV + yy * 139 + 2 * ox;
            float acc = 0.f;
            #pragma unroll
            for (int tp = 0; tp < 12; tp++) acc += fdr[tp] * src[tp];
            out[(size_t)nc * 4096 + (oy0 + yy) * 64 + ox] = acc;
        }
        __syncthreads();
    }
}

// ---------------- launch ----------------
extern "C" void kernel_launch(void* const* d_in, const int* in_sizes, int n_in,
                              void* d_out, int out_size) {
    const float* x  = (const float*)d_in[0];
    const float* w  = (const float*)d_in[1];
    const float* aw = (const float*)d_in[2];
    const float* ab = (const float*)d_in[3];
    const float* cw = (const float*)d_in[4];
    const float* cb = (const float*)d_in[5];
    const float* fu = (const float*)d_in[6];
    const float* fd = (const float*)d_in[7];
    float* out = (float*)d_out;

    cudaFuncSetAttribute(k_conv, cudaFuncAttributeMaxDynamicSharedMemorySize, CONV_SMEM);
    cudaFuncSetAttribute(k_fir,  cudaFuncAttributeMaxDynamicSharedMemorySize, FIR_SMEM);

    k_styles<<<NB, 512>>>(w, aw, ab);
    k_norm_s<<<NB, 512>>>();
    k_wt<<<CO, 512>>>(cw);
    k_d<<<(NB * CO) / 256, 256>>>();
    k_xsplit<<<dim3(68, NB), 256>>>(x);

    k_conv<<<dim3(4, 36, NB), 256, CONV_SMEM>>>(cb);

    k_fir<<<NB * CO, 256, FIR_SMEM>>>(fu, fd, out);
}

// round 12
// speedup vs baseline: 9.5485x; 1.2028x over previous
#include <cuda_runtime.h>
#include <cuda_fp16.h>
#include <cstdint>
#include <math.h>

#define NB 16
#define CI 512
#define CO 512
#define RES 64
#define YS 66
#define YPAD 4608
#define OS 64
#define NT 1089      // 33x33 winograd tiles
#define NTP 1152     // padded tiles (9*128)

// ---------------- scratch (device globals) ----------------
__device__ float g_styles[NB * CI];
__device__ float g_s[NB * CI];
__device__ float g_ssum16[NB];
__device__ float g_q[CO * CI];
__device__ float g_d[NB * CO];
__device__ __half g_wt16[16 * CO * CI];                  // [comp][oc][ci]  8.4MB
__device__ __half g_xt[(size_t)NB * 16 * NTP * CI];      // [n][comp][tile][ci] 302MB
__device__ float  g_m[(size_t)NB * CO * 16 * NTP];       // [n][oc][comp][tile] 604MB
__device__ float  g_y[(size_t)NB * CO * YPAD];           // 151MB

// ---------------- helpers ----------------
__device__ __forceinline__ uint32_t smem_u32(const void* p) {
    uint32_t a;
    asm("{ .reg .u64 t; cvta.to.shared.u64 t, %1; cvt.u32.u64 %0, t; }" : "=r"(a) : "l"(p));
    return a;
}
__device__ __forceinline__ void cp16(uint32_t dst, const void* src) {
    asm volatile("cp.async.cg.shared.global [%0], [%1], 16;" :: "r"(dst), "l"(src));
}
__device__ __forceinline__ void ldsm4(uint32_t* r, uint32_t addr) {
    asm volatile("ldmatrix.sync.aligned.m8n8.x4.shared.b16 {%0,%1,%2,%3}, [%4];"
                 : "=r"(r[0]), "=r"(r[1]), "=r"(r[2]), "=r"(r[3]) : "r"(addr));
}
__device__ __forceinline__ void mma16816(float* c, const uint32_t* a, uint32_t b0, uint32_t b1) {
    asm volatile(
        "mma.sync.aligned.m16n8k16.row.col.f32.f16.f16.f32 "
        "{%0,%1,%2,%3}, {%4,%5,%6,%7}, {%8,%9}, {%0,%1,%2,%3};"
        : "+f"(c[0]), "+f"(c[1]), "+f"(c[2]), "+f"(c[3])
        : "r"(a[0]), "r"(a[1]), "r"(a[2]), "r"(a[3]), "r"(b0), "r"(b1));
}

// ---------------- setup kernels ----------------
__global__ void k_styles(const float* __restrict__ w,
                         const float* __restrict__ aw,
                         const float* __restrict__ ab) {
    int n = blockIdx.x, c = threadIdx.x;
    const float* wr = w + n * 512;
    const float* ar = aw + c * 512;
    float acc = 0.f;
    #pragma unroll 8
    for (int k = 0; k < 512; k++) acc += wr[k] * ar[k];
    float st = acc * 0.044194173824159216f + ab[c];
    g_styles[n * CI + c] = st;
    float v = st * st;
    #pragma unroll
    for (int off = 16; off; off >>= 1) v += __shfl_down_sync(0xffffffffu, v, off);
    __shared__ float ps[16];
    if ((c & 31) == 0) ps[c >> 5] = v;
    __syncthreads();
    if (c == 0) {
        float tot = 0.f;
        #pragma unroll
        for (int k = 0; k < 16; k++) tot += ps[k];
        g_ssum16[n] = tot;
    }
}

__global__ void k_norm_s() {
    int i = blockIdx.x * 512 + threadIdx.x;
    float tot = 0.f;
    #pragma unroll
    for (int k = 0; k < NB; k++) tot += g_ssum16[k];
    float msr = rsqrtf(tot * (1.0f / (NB * CI)));
    g_s[i] = g_styles[i] * msr;
}

// normalize weights, Winograd-transform to fp16 [comp][oc][ci], compute q
__global__ void k_wt(const float* __restrict__ cw) {
    int o = blockIdx.x, i = threadIdx.x;
    float g9[9]; float ss = 0.f;
    const float* p = cw + (o * CI + i) * 9;
    #pragma unroll
    for (int k = 0; k < 9; k++) { g9[k] = p[k]; ss += g9[k] * g9[k]; }
    __shared__ float red[512];
    red[i] = ss;
    __syncthreads();
    for (int s = 256; s; s >>= 1) { if (i < s) red[i] += red[i + s]; __syncthreads(); }
    float inv = rsqrtf(red[0] * (1.0f / 4608.0f));
    float g[3][3];
    #pragma unroll
    for (int k = 0; k < 9; k++) g[k / 3][k % 3] = g9[k] * inv;
    // r = G g  (rows 4 x 3)
    float r[4][3];
    #pragma unroll
    for (int j = 0; j < 3; j++) {
        r[0][j] = g[0][j];
        r[1][j] = 0.5f * (g[0][j] + g[1][j] + g[2][j]);
        r[2][j] = 0.5f * (g[0][j] - g[1][j] + g[2][j]);
        r[3][j] = g[2][j];
    }
    // gt = r G^T  (4x4)
    #pragma unroll
    for (int u = 0; u < 4; u++) {
        float gt0 = r[u][0];
        float gt1 = 0.5f * (r[u][0] + r[u][1] + r[u][2]);
        float gt2 = 0.5f * (r[u][0] - r[u][1] + r[u][2]);
        float gt3 = r[u][2];
        g_wt16[((u * 4 + 0) * 512 + o) * 512 + i] = __float2half_rn(gt0);
        g_wt16[((u * 4 + 1) * 512 + o) * 512 + i] = __float2half_rn(gt1);
        g_wt16[((u * 4 + 2) * 512 + o) * 512 + i] = __float2half_rn(gt2);
        g_wt16[((u * 4 + 3) * 512 + o) * 512 + i] = __float2half_rn(gt3);
    }
    g_q[o * CI + i] = ss * inv * inv;
}

// warp-per-(n,o) demod
__global__ void k_d() {
    int gw = blockIdx.x * 8 + (threadIdx.x >> 5);   // 0..8191
    int lane = threadIdx.x & 31;
    int n = gw & 15, o = gw >> 4;
    const float* sp = g_s + n * CI;
    const float* qp = g_q + o * CI;
    float acc = 0.f;
    #pragma unroll 4
    for (int i = lane; i < 512; i += 32) { float sv = sp[i]; acc += sv * sv * qp[i]; }
    #pragma unroll
    for (int off = 16; off; off >>= 1) acc += __shfl_down_sync(0xffffffffu, acc, off);
    if (lane == 0) g_d[n * CO + o] = rsqrtf(acc + 1e-8f);
}

// ---------------- input transform: modulate, pad, B^T d B -> fp16 [n][comp][tile][ci]
#define XT_SMEM (4 * 68 * 65 * 4)
__global__ void __launch_bounds__(256, 2) k_xtrans(const float* __restrict__ x) {
    extern __shared__ float s[];   // [i 4][col 68][ci 64] stride 65
    int ty = blockIdx.x;   // 0..32
    int n  = blockIdx.y;
    int t  = threadIdx.x;
    const float* sp = g_s + n * 512;

    for (int ic0 = 0; ic0 < 512; ic0 += 64) {
        __syncthreads();
        // load 4 rows x 68 cols x 64 ci (modulated, zero-padded)
        for (int e = t; e < 4 * 68 * 64; e += 256) {
            int col = e % 68; int rest = e / 68;
            int i = rest & 3, ci = rest >> 2;
            int xr = 2 * ty + i - 2, xc = col - 2;
            float v = 0.f;
            if (xr >= 0 && xr < 64 && xc >= 0 && xc < 64)
                v = x[(((size_t)n * 512 + ic0 + ci) * 64 + xr) * 64 + xc] * sp[ic0 + ci];
            s[(i * 68 + col) * 65 + ci] = v;
        }
        __syncthreads();
        // transform: 33 tx x 64 ci
        int ci = t & 63, txi = t >> 6;
        for (int pss = 0; pss < 9; pss++) {
            int tx = pss * 4 + txi;
            if (tx < 33) {
                float d[4][4];
                #pragma unroll
                for (int i = 0; i < 4; i++)
                    #pragma unroll
                    for (int j = 0; j < 4; j++)
                        d[i][j] = s[(i * 68 + 2 * tx + j) * 65 + ci];
                float tr[4][4];
                #pragma unroll
                for (int j = 0; j < 4; j++) {
                    tr[0][j] = d[0][j] - d[2][j];
                    tr[1][j] = d[1][j] + d[2][j];
                    tr[2][j] = d[2][j] - d[1][j];
                    tr[3][j] = d[1][j] - d[3][j];
                }
                int tile = ty * 33 + tx;
                #pragma unroll
                for (int u = 0; u < 4; u++) {
                    float d0 = tr[u][0] - tr[u][2];
                    float d1 = tr[u][1] + tr[u][2];
                    float d2 = tr[u][2] - tr[u][1];
                    float d3 = tr[u][1] - tr[u][3];
                    size_t b0 = ((size_t)((n * 16 + u * 4 + 0)) * NTP + tile) * 512 + ic0 + ci;
                    size_t b1 = ((size_t)((n * 16 + u * 4 + 1)) * NTP + tile) * 512 + ic0 + ci;
                    size_t b2 = ((size_t)((n * 16 + u * 4 + 2)) * NTP + tile) * 512 + ic0 + ci;
                    size_t b3 = ((size_t)((n * 16 + u * 4 + 3)) * NTP + tile) * 512 + ic0 + ci;
                    g_xt[b0] = __float2half_rn(d0);
                    g_xt[b1] = __float2half_rn(d1);
                    g_xt[b2] = __float2half_rn(d2);
                    g_xt[b3] = __float2half_rn(d3);
                }
            }
        }
    }
}

// ---------------- winograd GEMM: per comp, M[n][oc][comp][tile] ----------------
#define ROWB 144
#define TILEB 18432
#define STAGEB 36864
#define CONV_SMEM (2 * STAGEB)

__global__ void __launch_bounds__(256, 2) k_conv() {
    extern __shared__ char smem[];
    uint32_t sb = smem_u32(smem);
    int t = threadIdx.x, wid = t >> 5, lane = t & 31;
    int wm = wid & 1, wn = wid >> 1;
    int oc0 = blockIdx.x * 128;
    int t0  = blockIdx.y * 128;
    int n   = blockIdx.z;

    auto stage_issue = [&](int it, int buf) {
        int comp = it >> 3, ch = it & 7;
        int ic0 = ch << 6;
        const __half* ah = g_wt16 + ((size_t)(comp * 512 + oc0)) * 512 + ic0;
        const __half* bh = g_xt + ((size_t)(n * 16 + comp) * NTP + t0) * 512 + ic0;
        uint32_t sbase = sb + buf * STAGEB;
        #pragma unroll
        for (int j = 0; j < 8; j++) {
            int id = j * 256 + t;
            int tile = id >> 10, e = id & 1023;
            int row = e >> 3, c16 = e & 7;
            const __half* src = tile ? bh : ah;
            cp16(sbase + tile * TILEB + row * ROWB + c16 * 16,
                 src + (size_t)row * 512 + c16 * 8);
        }
        asm volatile("cp.async.commit_group;" ::: "memory");
    };

    stage_issue(0, 0);

    int rl = lane & 15, chh = lane >> 4;
    int g4 = lane >> 2, t4 = lane & 3;
    float* mbase = g_m + (((size_t)(n * 512 + oc0) * 16) * NTP + t0);

    for (int comp = 0; comp < 16; comp++) {
        float acc[4][4][4];
        #pragma unroll
        for (int mi = 0; mi < 4; mi++)
            #pragma unroll
            for (int ni = 0; ni < 4; ni++)
                #pragma unroll
                for (int q = 0; q < 4; q++) acc[mi][ni][q] = 0.f;

        #pragma unroll 1
        for (int ch = 0; ch < 8; ch++) {
            int it = comp * 8 + ch;
            int buf = it & 1;
            if (it + 1 < 128) {
                stage_issue(it + 1, buf ^ 1);
                asm volatile("cp.async.wait_group 1;" ::: "memory");
            } else {
                asm volatile("cp.async.wait_group 0;" ::: "memory");
            }
            __syncthreads();

            uint32_t At = sb + buf * STAGEB;
            uint32_t Bt = At + TILEB;
            #pragma unroll
            for (int kk = 0; kk < 4; kk++) {
                uint32_t kb = (kk * 2 + chh) * 16;
                uint32_t a[4][4], b[2][4];
                #pragma unroll
                for (int nj = 0; nj < 2; nj++)
                    ldsm4(b[nj], Bt + (wn * 32 + nj * 16 + rl) * ROWB + kb);
                #pragma unroll
                for (int mi = 0; mi < 4; mi++)
                    ldsm4(a[mi], At + (wm * 64 + mi * 16 + rl) * ROWB + kb);
                #pragma unroll
                for (int mi = 0; mi < 4; mi++)
                    #pragma unroll
                    for (int ni = 0; ni < 4; ni++) {
                        int nj = ni >> 1, sub = ni & 1;
                        mma16816(acc[mi][ni], a[mi], b[nj][sub], b[nj][sub + 2]);
                    }
            }
            __syncthreads();
        }

        // write m for this comp
        float* mc = mbase + (size_t)comp * NTP;
        #pragma unroll
        for (int mi = 0; mi < 4; mi++) {
            int oa = wm * 64 + mi * 16 + g4;
            float* pa = mc + (size_t)oa * 16 * NTP;
            float* pb = mc + (size_t)(oa + 8) * 16 * NTP;
            #pragma unroll
            for (int ni = 0; ni < 4; ni++) {
                int px = wn * 32 + ni * 8 + t4 * 2;
                float2 va, vb;
                va.x = acc[mi][ni][0]; va.y = acc[mi][ni][1];
                vb.x = acc[mi][ni][2]; vb.y = acc[mi][ni][3];
                *(float2*)(pa + px) = va;
                *(float2*)(pb + px) = vb;
            }
        }
    }
}

// ---------------- output transform: y = A^T m A, demod + bias -> g_y ----------------
__global__ void __launch_bounds__(256) k_wout(const float* __restrict__ cb) {
    __shared__ float yimg[4488];   // 66 rows x 68 stride
    int oc = blockIdx.x, n = blockIdx.y, t = threadIdx.x;
    for (int e = t; e < 4488; e += 256) yimg[e] = 0.f;
    __syncthreads();

    const float* mb = g_m + ((size_t)(n * 512 + oc) * 16) * NTP;
    float dd = g_d[n * CO + oc];
    float bias = cb[oc];

    for (int tile = t; tile < NT; tile += 256) {
        float m[16];
        #pragma unroll
        for (int c = 0; c < 16; c++) m[c] = mb[(size_t)c * NTP + tile];
        float s0[4], s1[4];
        #pragma unroll
        for (int v = 0; v < 4; v++) {
            s0[v] = m[v] + m[4 + v] + m[8 + v];
            s1[v] = m[4 + v] - m[8 + v] - m[12 + v];
        }
        float y00 = s0[0] + s0[1] + s0[2], y01 = s0[1] - s0[2] - s0[3];
        float y10 = s1[0] + s1[1] + s1[2], y11 = s1[1] - s1[2] - s1[3];
        int ty = tile / 33, tx = tile - ty * 33;
        int off = (2 * ty) * 68 + 2 * tx;
        yimg[off]      = y00 * dd + bias;
        yimg[off + 1]  = y01 * dd + bias;
        yimg[off + 68] = y10 * dd + bias;
        yimg[off + 69] = y11 * dd + bias;
    }
    __syncthreads();

    float4* gy = (float4*)(g_y + (size_t)(n * 512 + oc) * YPAD);
    float4* yi4 = (float4*)yimg;
    for (int e = t; e < 1122; e += 256) gy[e] = yi4[e];
}

// ---------------- fused filtered_lrelu (unchanged from R11) ----------------
#define F_SY 0
#define F_SUV 5032
#define F_SU 15520
#define F_SDV 21358
#define FIR_SMEM (23582 * 4)
#define LRC1 5.656854249492381f
#define LRC2 1.1313708498984762f

__global__ void __launch_bounds__(256, 2) k_fir(const float* __restrict__ fu,
                                                const float* __restrict__ fd,
                                                float* __restrict__ out) {
    extern __shared__ float sm[];
    float* sY  = sm + F_SY;
    float* sUV = sm + F_SUV;
    float* sU  = sm + F_SU;
    float* sDV = sm + F_SDV;
    int t = threadIdx.x;
    int nc = blockIdx.x;

    float fe[6], fo[6], fdr[12];
    #pragma unroll
    for (int j = 0; j < 6; j++) { fe[j] = fu[2 * j]; fo[j] = fu[2 * j + 1]; }
    #pragma unroll
    for (int j = 0; j < 12; j++) fdr[j] = fd[j];

    float4* sY4 = (float4*)sY;
    const float4* gy = (const float4*)(g_y + (size_t)nc * YPAD);
    for (int e = t; e < 1122; e += 256) sY4[68 + e] = gy[e];
    float4 z4 = make_float4(0.f, 0.f, 0.f, 0.f);
    for (int e = t; e < 136; e += 256) sY4[(e < 68) ? e : (1122 + e)] = z4;
    for (int e = t; e < 138 * 8; e += 256) {
        int r = e >> 3, c = e & 7;
        sUV[r * 76 + ((c < 4) ? c : (66 + c))] = 0.f;
    }
    __syncthreads();

    for (int e = t; e < 69 * 66; e += 256) {
        int q = e / 66, xx = e - q * 66;
        const float* src = sY + q * 68 + xx;
        float ve = 0.f, vo = 0.f;
        #pragma unroll
        for (int j = 0; j < 6; j++) {
            float s = src[j * 68];
            ve += fo[j] * s;
            vo += fe[j] * s;
        }
        sUV[(2 * q) * 76 + 4 + xx] = ve;
        sUV[(2 * q + 1) * 76 + 4 + xx] = vo;
    }
    __syncthreads();

    for (int oy0 = 0; oy0 < 64; oy0 += 16) {
        for (int e = t; e < 42 * 69; e += 256) {
            int rr = e / 69, q = e - rr * 69;
            const float* src = sUV + (2 * oy0 + rr) * 76 + q;
            float ve = 0.f, vo = 0.f;
            #pragma unroll
            for (int j = 0; j < 6; j++) {
                float s = src[j];
                ve += fo[j] * s;
                vo += fe[j] * s;
            }
            float w0 = fminf(fmaxf(fmaxf(ve * LRC1, ve * LRC2), -256.f), 256.f);
            float w1 = fminf(fmaxf(fmaxf(vo * LRC1, vo * LRC2), -256.f), 256.f);
            sU[rr * 139 + 2 * q] = w0;
            sU[rr * 139 + 2 * q + 1] = w1;
        }
        __syncthreads();
        for (int e = t; e < 16 * 138; e += 256) {
            int yy = e / 138, c = e - yy * 138;
            const float* src = sU + 2 * yy * 139 + c;
            float acc = 0.f;
            #pragma unroll
            for (int tp = 0; tp < 12; tp++) acc += fdr[tp] * src[tp * 139];
            sDV[yy * 139 + c] = acc;
        }
        __syncthreads();
        for (int e = t; e < 16 * 64; e += 256) {
            int yy = e >> 6, ox = e & 63;
            const float* src = sDV + yy * 139 + 2 * ox;
            float acc = 0.f;
            #pragma unroll
            for (int tp = 0; tp < 12; tp++) acc += fdr[tp] * src[tp];
            out[(size_t)nc * 4096 + (oy0 + yy) * 64 + ox] = acc;
        }
        __syncthreads();
    }
}

// ---------------- launch ----------------
extern "C" void kernel_launch(void* const* d_in, const int* in_sizes, int n_in,
                              void* d_out, int out_size) {
    const float* x  = (const float*)d_in[0];
    const float* w  = (const float*)d_in[1];
    const float* aw = (const float*)d_in[2];
    const float* ab = (const float*)d_in[3];
    const float* cw = (const float*)d_in[4];
    const float* cb = (const float*)d_in[5];
    const float* fu = (const float*)d_in[6];
    const float* fd = (const float*)d_in[7];
    float* out = (float*)d_out;

    cudaFuncSetAttribute(k_conv,   cudaFuncAttributeMaxDynamicSharedMemorySize, CONV_SMEM);
    cudaFuncSetAttribute(k_fir,    cudaFuncAttributeMaxDynamicSharedMemorySize, FIR_SMEM);
    cudaFuncSetAttribute(k_xtrans, cudaFuncAttributeMaxDynamicSharedMemorySize, XT_SMEM);

    k_styles<<<NB, 512>>>(w, aw, ab);
    k_norm_s<<<NB, 512>>>();
    k_wt<<<CO, 512>>>(cw);
    k_d<<<1024, 256>>>();
    k_xtrans<<<dim3(33, NB), 256, XT_SMEM>>>(x);

    k_conv<<<dim3(4, 9, NB), 256, CONV_SMEM>>>();

    k_wout<<<dim3(CO, NB), 256>>>(cb);
    k_fir<<<NB * CO, 256, FIR_SMEM>>>(fu, fd, out);
}

// round 13
// speedup vs baseline: 10.0784x; 1.0555x over previous
#include <cuda_runtime.h>
#include <cuda_fp16.h>
#include <cstdint>
#include <math.h>

#define NB 16
#define CI 512
#define CO 512
#define RES 64
#define OS 64
#define NT 1089      // 33x33 winograd tiles
#define NTP 1152     // padded tiles (9*128)

// ---------------- scratch (device globals) ----------------
__device__ float g_styles[NB * CI];
__device__ float g_s[NB * CI];
__device__ float g_ssum16[NB];
__device__ float g_q[CO * CI];
__device__ float g_d[NB * CO];
__device__ __half g_wt16[16 * CO * CI];                  // [comp][oc][ci]  8.4MB
__device__ __half g_xt[(size_t)NB * 16 * NTP * CI];      // [n][comp][tile][ci] 302MB
__device__ float  g_m[(size_t)NB * CO * 16 * NTP];       // [n][oc][comp][tile] 604MB

// ---------------- helpers ----------------
__device__ __forceinline__ uint32_t smem_u32(const void* p) {
    uint32_t a;
    asm("{ .reg .u64 t; cvta.to.shared.u64 t, %1; cvt.u32.u64 %0, t; }" : "=r"(a) : "l"(p));
    return a;
}
__device__ __forceinline__ void cp16(uint32_t dst, const void* src) {
    asm volatile("cp.async.cg.shared.global [%0], [%1], 16;" :: "r"(dst), "l"(src));
}
__device__ __forceinline__ void ldsm4(uint32_t* r, uint32_t addr) {
    asm volatile("ldmatrix.sync.aligned.m8n8.x4.shared.b16 {%0,%1,%2,%3}, [%4];"
                 : "=r"(r[0]), "=r"(r[1]), "=r"(r[2]), "=r"(r[3]) : "r"(addr));
}
__device__ __forceinline__ void mma16816(float* c, const uint32_t* a, uint32_t b0, uint32_t b1) {
    asm volatile(
        "mma.sync.aligned.m16n8k16.row.col.f32.f16.f16.f32 "
        "{%0,%1,%2,%3}, {%4,%5,%6,%7}, {%8,%9}, {%0,%1,%2,%3};"
        : "+f"(c[0]), "+f"(c[1]), "+f"(c[2]), "+f"(c[3])
        : "r"(a[0]), "r"(a[1]), "r"(a[2]), "r"(a[3]), "r"(b0), "r"(b1));
}

// ---------------- setup kernels ----------------
__global__ void k_styles(const float* __restrict__ w,
                         const float* __restrict__ aw,
                         const float* __restrict__ ab) {
    int n = blockIdx.x, c = threadIdx.x;
    const float* wr = w + n * 512;
    const float* ar = aw + c * 512;
    float acc = 0.f;
    #pragma unroll 8
    for (int k = 0; k < 512; k++) acc += wr[k] * ar[k];
    float st = acc * 0.044194173824159216f + ab[c];
    g_styles[n * CI + c] = st;
    float v = st * st;
    #pragma unroll
    for (int off = 16; off; off >>= 1) v += __shfl_down_sync(0xffffffffu, v, off);
    __shared__ float ps[16];
    if ((c & 31) == 0) ps[c >> 5] = v;
    __syncthreads();
    if (c == 0) {
        float tot = 0.f;
        #pragma unroll
        for (int k = 0; k < 16; k++) tot += ps[k];
        g_ssum16[n] = tot;
    }
}

__global__ void k_norm_s() {
    int i = blockIdx.x * 512 + threadIdx.x;
    float tot = 0.f;
    #pragma unroll
    for (int k = 0; k < NB; k++) tot += g_ssum16[k];
    float msr = rsqrtf(tot * (1.0f / (NB * CI)));
    g_s[i] = g_styles[i] * msr;
}

// normalize weights, Winograd-transform to fp16 [comp][oc][ci], compute q
__global__ void k_wt(const float* __restrict__ cw) {
    int o = blockIdx.x, i = threadIdx.x;
    float g9[9]; float ss = 0.f;
    const float* p = cw + (o * CI + i) * 9;
    #pragma unroll
    for (int k = 0; k < 9; k++) { g9[k] = p[k]; ss += g9[k] * g9[k]; }
    __shared__ float red[512];
    red[i] = ss;
    __syncthreads();
    for (int s = 256; s; s >>= 1) { if (i < s) red[i] += red[i + s]; __syncthreads(); }
    float inv = rsqrtf(red[0] * (1.0f / 4608.0f));
    float g[3][3];
    #pragma unroll
    for (int k = 0; k < 9; k++) g[k / 3][k % 3] = g9[k] * inv;
    float r[4][3];
    #pragma unroll
    for (int j = 0; j < 3; j++) {
        r[0][j] = g[0][j];
        r[1][j] = 0.5f * (g[0][j] + g[1][j] + g[2][j]);
        r[2][j] = 0.5f * (g[0][j] - g[1][j] + g[2][j]);
        r[3][j] = g[2][j];
    }
    #pragma unroll
    for (int u = 0; u < 4; u++) {
        float gt0 = r[u][0];
        float gt1 = 0.5f * (r[u][0] + r[u][1] + r[u][2]);
        float gt2 = 0.5f * (r[u][0] - r[u][1] + r[u][2]);
        float gt3 = r[u][2];
        g_wt16[((u * 4 + 0) * 512 + o) * 512 + i] = __float2half_rn(gt0);
        g_wt16[((u * 4 + 1) * 512 + o) * 512 + i] = __float2half_rn(gt1);
        g_wt16[((u * 4 + 2) * 512 + o) * 512 + i] = __float2half_rn(gt2);
        g_wt16[((u * 4 + 3) * 512 + o) * 512 + i] = __float2half_rn(gt3);
    }
    g_q[o * CI + i] = ss * inv * inv;
}

// warp-per-(n,o) demod
__global__ void k_d() {
    int gw = blockIdx.x * 8 + (threadIdx.x >> 5);
    int lane = threadIdx.x & 31;
    int n = gw & 15, o = gw >> 4;
    const float* sp = g_s + n * CI;
    const float* qp = g_q + o * CI;
    float acc = 0.f;
    #pragma unroll 4
    for (int i = lane; i < 512; i += 32) { float sv = sp[i]; acc += sv * sv * qp[i]; }
    #pragma unroll
    for (int off = 16; off; off >>= 1) acc += __shfl_down_sync(0xffffffffu, acc, off);
    if (lane == 0) g_d[n * CO + o] = rsqrtf(acc + 1e-8f);
}

// ---------------- input transform: modulate, pad, B^T d B -> fp16 [n][comp][tile][ci]
#define XT_SMEM (4 * 68 * 65 * 4)
__global__ void __launch_bounds__(256, 2) k_xtrans(const float* __restrict__ x) {
    extern __shared__ float s[];   // [i 4][col 68][ci 64] stride 65
    int ty = blockIdx.x;   // 0..32
    int n  = blockIdx.y;
    int t  = threadIdx.x;
    const float* sp = g_s + n * 512;

    for (int ic0 = 0; ic0 < 512; ic0 += 64) {
        __syncthreads();
        for (int e = t; e < 4 * 68 * 64; e += 256) {
            int col = e % 68; int rest = e / 68;
            int i = rest & 3, ci = rest >> 2;
            int xr = 2 * ty + i - 2, xc = col - 2;
            float v = 0.f;
            if (xr >= 0 && xr < 64 && xc >= 0 && xc < 64)
                v = x[(((size_t)n * 512 + ic0 + ci) * 64 + xr) * 64 + xc] * sp[ic0 + ci];
            s[(i * 68 + col) * 65 + ci] = v;
        }
        __syncthreads();
        int ci = t & 63, txi = t >> 6;
        for (int pss = 0; pss < 9; pss++) {
            int tx = pss * 4 + txi;
            if (tx < 33) {
                float d[4][4];
                #pragma unroll
                for (int i = 0; i < 4; i++)
                    #pragma unroll
                    for (int j = 0; j < 4; j++)
                        d[i][j] = s[(i * 68 + 2 * tx + j) * 65 + ci];
                float tr[4][4];
                #pragma unroll
                for (int j = 0; j < 4; j++) {
                    tr[0][j] = d[0][j] - d[2][j];
                    tr[1][j] = d[1][j] + d[2][j];
                    tr[2][j] = d[2][j] - d[1][j];
                    tr[3][j] = d[1][j] - d[3][j];
                }
                int tile = ty * 33 + tx;
                #pragma unroll
                for (int u = 0; u < 4; u++) {
                    float d0 = tr[u][0] - tr[u][2];
                    float d1 = tr[u][1] + tr[u][2];
                    float d2 = tr[u][2] - tr[u][1];
                    float d3 = tr[u][1] - tr[u][3];
                    size_t b0 = ((size_t)((n * 16 + u * 4 + 0)) * NTP + tile) * 512 + ic0 + ci;
                    size_t b1 = ((size_t)((n * 16 + u * 4 + 1)) * NTP + tile) * 512 + ic0 + ci;
                    size_t b2 = ((size_t)((n * 16 + u * 4 + 2)) * NTP + tile) * 512 + ic0 + ci;
                    size_t b3 = ((size_t)((n * 16 + u * 4 + 3)) * NTP + tile) * 512 + ic0 + ci;
                    g_xt[b0] = __float2half_rn(d0);
                    g_xt[b1] = __float2half_rn(d1);
                    g_xt[b2] = __float2half_rn(d2);
                    g_xt[b3] = __float2half_rn(d3);
                }
            }
        }
    }
}

// ---------------- winograd GEMM: per comp, M[n][oc][comp][tile] ----------------
#define ROWB 144
#define TILEB 18432
#define STAGEB 36864
#define CONV_SMEM (2 * STAGEB)

__global__ void __launch_bounds__(256, 2) k_conv() {
    extern __shared__ char smem[];
    uint32_t sb = smem_u32(smem);
    int t = threadIdx.x, wid = t >> 5, lane = t & 31;
    int wm = wid & 1, wn = wid >> 1;
    int oc0 = blockIdx.x * 128;
    int t0  = blockIdx.y * 128;
    int n   = blockIdx.z;

    auto stage_issue = [&](int it, int buf) {
        int comp = it >> 3, ch = it & 7;
        int ic0 = ch << 6;
        const __half* ah = g_wt16 + ((size_t)(comp * 512 + oc0)) * 512 + ic0;
        const __half* bh = g_xt + ((size_t)(n * 16 + comp) * NTP + t0) * 512 + ic0;
        uint32_t sbase = sb + buf * STAGEB;
        #pragma unroll
        for (int j = 0; j < 8; j++) {
            int id = j * 256 + t;
            int tile = id >> 10, e = id & 1023;
            int row = e >> 3, c16 = e & 7;
            const __half* src = tile ? bh : ah;
            cp16(sbase + tile * TILEB + row * ROWB + c16 * 16,
                 src + (size_t)row * 512 + c16 * 8);
        }
        asm volatile("cp.async.commit_group;" ::: "memory");
    };

    stage_issue(0, 0);

    int rl = lane & 15, chh = lane >> 4;
    int g4 = lane >> 2, t4 = lane & 3;
    float* mbase = g_m + (((size_t)(n * 512 + oc0) * 16) * NTP + t0);

    for (int comp = 0; comp < 16; comp++) {
        float acc[4][4][4];
        #pragma unroll
        for (int mi = 0; mi < 4; mi++)
            #pragma unroll
            for (int ni = 0; ni < 4; ni++)
                #pragma unroll
                for (int q = 0; q < 4; q++) acc[mi][ni][q] = 0.f;

        #pragma unroll 1
        for (int ch = 0; ch < 8; ch++) {
            int it = comp * 8 + ch;
            int buf = it & 1;
            if (it + 1 < 128) {
                stage_issue(it + 1, buf ^ 1);
                asm volatile("cp.async.wait_group 1;" ::: "memory");
            } else {
                asm volatile("cp.async.wait_group 0;" ::: "memory");
            }
            __syncthreads();

            uint32_t At = sb + buf * STAGEB;
            uint32_t Bt = At + TILEB;
            #pragma unroll
            for (int kk = 0; kk < 4; kk++) {
                uint32_t kb = (kk * 2 + chh) * 16;
                uint32_t a[4][4], b[2][4];
                #pragma unroll
                for (int nj = 0; nj < 2; nj++)
                    ldsm4(b[nj], Bt + (wn * 32 + nj * 16 + rl) * ROWB + kb);
                #pragma unroll
                for (int mi = 0; mi < 4; mi++)
                    ldsm4(a[mi], At + (wm * 64 + mi * 16 + rl) * ROWB + kb);
                #pragma unroll
                for (int mi = 0; mi < 4; mi++)
                    #pragma unroll
                    for (int ni = 0; ni < 4; ni++) {
                        int nj = ni >> 1, sub = ni & 1;
                        mma16816(acc[mi][ni], a[mi], b[nj][sub], b[nj][sub + 2]);
                    }
            }
            __syncthreads();
        }

        float* mc = mbase + (size_t)comp * NTP;
        #pragma unroll
        for (int mi = 0; mi < 4; mi++) {
            int oa = wm * 64 + mi * 16 + g4;
            float* pa = mc + (size_t)oa * 16 * NTP;
            float* pb = mc + (size_t)(oa + 8) * 16 * NTP;
            #pragma unroll
            for (int ni = 0; ni < 4; ni++) {
                int px = wn * 32 + ni * 8 + t4 * 2;
                float2 va, vb;
                va.x = acc[mi][ni][0]; va.y = acc[mi][ni][1];
                vb.x = acc[mi][ni][2]; vb.y = acc[mi][ni][3];
                *(float2*)(pa + px) = va;
                *(float2*)(pb + px) = vb;
            }
        }
    }
}

// ---------------- fused output-transform + filtered_lrelu: one CTA per (n,oc) ----------------
// sY: 74 rows x 68 (rows 0-3, 70-73 zero; rows 4..69 = y rows 0..65)
#define F_SY 0
#define F_SUV 5032
#define F_SU 15520
#define F_SDV 21358
#define FIR_SMEM (23582 * 4)
#define LRC1 5.656854249492381f
#define LRC2 1.1313708498984762f

__global__ void __launch_bounds__(256, 2) k_fir(const float* __restrict__ fu,
                                                const float* __restrict__ fd,
                                                const float* __restrict__ cb,
                                                float* __restrict__ out) {
    extern __shared__ float sm[];
    float* sY  = sm + F_SY;
    float* sUV = sm + F_SUV;
    float* sU  = sm + F_SU;
    float* sDV = sm + F_SDV;
    int t = threadIdx.x;
    int nc = blockIdx.x;            // n*512 + oc
    int oc = nc & 511;

    float fe[6], fo[6], fdr[12];
    #pragma unroll
    for (int j = 0; j < 6; j++) { fe[j] = fu[2 * j]; fo[j] = fu[2 * j + 1]; }
    #pragma unroll
    for (int j = 0; j < 12; j++) fdr[j] = fd[j];

    // zero entire sY (padded 74x68), zero sUV pad cols
    float4* sY4 = (float4*)sY;
    float4 z4 = make_float4(0.f, 0.f, 0.f, 0.f);
    for (int e = t; e < 1258; e += 256) sY4[e] = z4;
    for (int e = t; e < 138 * 8; e += 256) {
        int r = e >> 3, c = e & 7;
        sUV[r * 76 + ((c < 4) ? c : (66 + c))] = 0.f;
    }
    __syncthreads();

    // output transform: m[16] -> 2x2 pixels, demod + bias, into sY (rows offset +4)
    {
        const float* mb = g_m + ((size_t)nc * 16) * NTP;
        float dd = g_d[nc];
        float bias = cb[oc];
        for (int tile = t; tile < NT; tile += 256) {
            float m[16];
            #pragma unroll
            for (int c = 0; c < 16; c++) m[c] = mb[(size_t)c * NTP + tile];
            float s0[4], s1[4];
            #pragma unroll
            for (int v = 0; v < 4; v++) {
                s0[v] = m[v] + m[4 + v] + m[8 + v];
                s1[v] = m[4 + v] - m[8 + v] - m[12 + v];
            }
            float y00 = s0[0] + s0[1] + s0[2], y01 = s0[1] - s0[2] - s0[3];
            float y10 = s1[0] + s1[1] + s1[2], y11 = s1[1] - s1[2] - s1[3];
            int ty = tile / 33, tx = tile - ty * 33;
            int off = (4 + 2 * ty) * 68 + 2 * tx;
            sY[off]      = y00 * dd + bias;
            sY[off + 1]  = y01 * dd + bias;
            sY[off + 68] = y10 * dd + bias;
            sY[off + 69] = y11 * dd + bias;
        }
    }
    __syncthreads();

    // up-vertical, paired parity
    for (int e = t; e < 69 * 66; e += 256) {
        int q = e / 66, xx = e - q * 66;
        const float* src = sY + q * 68 + xx;
        float ve = 0.f, vo = 0.f;
        #pragma unroll
        for (int j = 0; j < 6; j++) {
            float s = src[j * 68];
            ve += fo[j] * s;
            vo += fe[j] * s;
        }
        sUV[(2 * q) * 76 + 4 + xx] = ve;
        sUV[(2 * q + 1) * 76 + 4 + xx] = vo;
    }
    __syncthreads();

    for (int oy0 = 0; oy0 < 64; oy0 += 16) {
        for (int e = t; e < 42 * 69; e += 256) {
            int rr = e / 69, q = e - rr * 69;
            const float* src = sUV + (2 * oy0 + rr) * 76 + q;
            float ve = 0.f, vo = 0.f;
            #pragma unroll
            for (int j = 0; j < 6; j++) {
                float s = src[j];
                ve += fo[j] * s;
                vo += fe[j] * s;
            }
            float w0 = fminf(fmaxf(fmaxf(ve * LRC1, ve * LRC2), -256.f), 256.f);
            float w1 = fminf(fmaxf(fmaxf(vo * LRC1, vo * LRC2), -256.f), 256.f);
            sU[rr * 139 + 2 * q] = w0;
            sU[rr * 139 + 2 * q + 1] = w1;
        }
        __syncthreads();
        for (int e = t; e < 16 * 138; e += 256) {
            int yy = e / 138, c = e - yy * 138;
            const float* src = sU + 2 * yy * 139 + c;
            float acc = 0.f;
            #pragma unroll
            for (int tp = 0; tp < 12; tp++) acc += fdr[tp] * src[tp * 139];
            sDV[yy * 139 + c] = acc;
        }
        __syncthreads();
        for (int e = t; e < 16 * 64; e += 256) {
            int yy = e >> 6, ox = e & 63;
            const float* src = sDV + yy * 139 + 2 * ox;
            float acc = 0.f;
            #pragma unroll
            for (int tp = 0; tp < 12; tp++) acc += fdr[tp] * src[tp];
            out[(size_t)nc * 4096 + (oy0 + yy) * 64 + ox] = acc;
        }
        __syncthreads();
    }
}

// ---------------- launch ----------------
extern "C" void kernel_launch(void* const* d_in, const int* in_sizes, int n_in,
                              void* d_out, int out_size) {
    const float* x  = (const float*)d_in[0];
    const float* w  = (const float*)d_in[1];
    const float* aw = (const float*)d_in[2];
    const float* ab = (const float*)d_in[3];
    const float* cw = (const float*)d_in[4];
    const float* cb = (const float*)d_in[5];
    const float* fu = (const float*)d_in[6];
    const float* fd = (const float*)d_in[7];
    float* out = (float*)d_out;

    cudaFuncSetAttribute(k_conv,   cudaFuncAttributeMaxDynamicSharedMemorySize, CONV_SMEM);
    cudaFuncSetAttribute(k_fir,    cudaFuncAttributeMaxDynamicSharedMemorySize, FIR_SMEM);
    cudaFuncSetAttribute(k_xtrans, cudaFuncAttributeMaxDynamicSharedMemorySize, XT_SMEM);

    k_styles<<<NB, 512>>>(w, aw, ab);
    k_norm_s<<<NB, 512>>>();
    k_wt<<<CO, 512>>>(cw);
    k_d<<<1024, 256>>>();
    k_xtrans<<<dim3(33, NB), 256, XT_SMEM>>>(x);

    k_conv<<<dim3(4, 9, NB), 256, CONV_SMEM>>>();

    k_fir<<<NB * CO, 256, FIR_SMEM>>>(fu, fd, cb, out);
}